// round 13
// baseline (speedup 1.0000x reference)
#include <cuda_runtime.h>
#include <cuda_bf16.h>
#include <cuda_fp16.h>
#include <math.h>
#include <stdint.h>

// ---------------------------------------------------------------------------
// Problem constants
// ---------------------------------------------------------------------------
#define BATCH 2
#define SEQ 2048
#define HIDDEN 1024
#define NHEAD 16
#define HDIM 64
#define M_TOK (BATCH * SEQ)          // 4096
#define QKV_N (3 * HIDDEN)           // 3072
#define LD32 (QKV_N / 2)             // 1536 u32 per token row (qkv planes)

// Scratch (__device__ globals per allocation rules)
__device__ uint32_t g_qh[(size_t)M_TOK * LD32];      // qkv hi plane (V range: fp16)
__device__ uint32_t g_ql[(size_t)M_TOK * LD32];      // qkv lo plane
__device__ float    g_attn[(size_t)M_TOK * HIDDEN];  // attention output fp32
__device__ int8_t   g_a1[(size_t)M_TOK * HIDDEN];    // attn digit1
__device__ int8_t   g_a2[(size_t)M_TOK * HIDDEN];    // attn digit2
__device__ int8_t   g_w1[(size_t)HIDDEN * HIDDEN];   // w_proj^T digit1 [n][k]
__device__ int8_t   g_w2[(size_t)HIDDEN * HIDDEN];   // w_proj^T digit2
__device__ unsigned g_maxA;                          // max|attn| (float bits)
__device__ unsigned g_maxW;                          // max|w_proj|

// ---------------------------------------------------------------------------
// Helpers
// ---------------------------------------------------------------------------
__device__ __forceinline__ void split2(float x, float y,
                                       uint32_t& hi, uint32_t& lo) {
    __nv_bfloat162 h = __floats2bfloat162_rn(x, y);
    float2 hf = __bfloat1622float2(h);
    __nv_bfloat162 l = __floats2bfloat162_rn(x - hf.x, y - hf.y);
    hi = *reinterpret_cast<uint32_t*>(&h);
    lo = *reinterpret_cast<uint32_t*>(&l);
}

__device__ __forceinline__ void split2h(float x, float y,
                                        uint32_t& hi, uint32_t& lo) {
    __half2 h = __floats2half2_rn(x, y);
    float2 hf = __half22float2(h);
    __half2 l = __floats2half2_rn(x - hf.x, y - hf.y);
    hi = *reinterpret_cast<uint32_t*>(&h);
    lo = *reinterpret_cast<uint32_t*>(&l);
}

__device__ __forceinline__ uint32_t pack_h2(float x, float y) {
    __half2 h = __floats2half2_rn(x, y);
    return *reinterpret_cast<uint32_t*>(&h);
}

__device__ __forceinline__ void mma_bf16(float* c, uint32_t a0, uint32_t a1,
                                         uint32_t a2, uint32_t a3,
                                         uint32_t b0, uint32_t b1) {
    asm volatile(
        "mma.sync.aligned.m16n8k16.row.col.f32.bf16.bf16.f32 "
        "{%0,%1,%2,%3}, {%4,%5,%6,%7}, {%8,%9}, {%0,%1,%2,%3};"
        : "+f"(c[0]), "+f"(c[1]), "+f"(c[2]), "+f"(c[3])
        : "r"(a0), "r"(a1), "r"(a2), "r"(a3), "r"(b0), "r"(b1));
}

__device__ __forceinline__ void mma_f16(float* c, uint32_t a0, uint32_t a1,
                                        uint32_t a2, uint32_t a3,
                                        uint32_t b0, uint32_t b1) {
    asm volatile(
        "mma.sync.aligned.m16n8k16.row.col.f32.f16.f16.f32 "
        "{%0,%1,%2,%3}, {%4,%5,%6,%7}, {%8,%9}, {%0,%1,%2,%3};"
        : "+f"(c[0]), "+f"(c[1]), "+f"(c[2]), "+f"(c[3])
        : "r"(a0), "r"(a1), "r"(a2), "r"(a3), "r"(b0), "r"(b1));
}

__device__ __forceinline__ void mma_s8(int* c, uint32_t a0, uint32_t a1,
                                       uint32_t a2, uint32_t a3,
                                       uint32_t b0, uint32_t b1) {
    asm volatile(
        "mma.sync.aligned.m16n8k32.row.col.s32.s8.s8.s32 "
        "{%0,%1,%2,%3}, {%4,%5,%6,%7}, {%8,%9}, {%0,%1,%2,%3};"
        : "+r"(c[0]), "+r"(c[1]), "+r"(c[2]), "+r"(c[3])
        : "r"(a0), "r"(a1), "r"(a2), "r"(a3), "r"(b0), "r"(b1));
}

__device__ __forceinline__ void ldsm4(uint32_t& r0, uint32_t& r1,
                                      uint32_t& r2, uint32_t& r3, uint32_t a) {
    asm volatile("ldmatrix.sync.aligned.m8n8.x4.shared.b16 {%0,%1,%2,%3}, [%4];"
                 : "=r"(r0), "=r"(r1), "=r"(r2), "=r"(r3) : "r"(a));
}

__device__ __forceinline__ void ldsm4t(uint32_t& r0, uint32_t& r1,
                                       uint32_t& r2, uint32_t& r3, uint32_t a) {
    asm volatile("ldmatrix.sync.aligned.m8n8.x4.trans.shared.b16 {%0,%1,%2,%3}, [%4];"
                 : "=r"(r0), "=r"(r1), "=r"(r2), "=r"(r3) : "r"(a));
}

__device__ __forceinline__ void cp16(uint32_t smem, const void* gmem) {
    asm volatile("cp.async.ca.shared.global [%0], [%1], 16;"
                 :: "r"(smem), "l"(gmem));
}
#define CP_COMMIT() asm volatile("cp.async.commit_group;" ::: "memory")
#define CP_WAIT(n)  asm volatile("cp.async.wait_group %0;" :: "n"(n) : "memory")

__device__ __forceinline__ void quant2(float x, float S, int8_t& d1, int8_t& d2) {
    int q = __float2int_rn(x * S);
    int q1 = (q + 128) >> 8;
    d1 = (int8_t)q1;
    d2 = (int8_t)(q - (q1 << 8));
}

// ---------------------------------------------------------------------------
// max-abs reduction (for w_proj)
// ---------------------------------------------------------------------------
__global__ __launch_bounds__(256)
void maxabs_kernel(const float* __restrict__ x, int n, unsigned* __restrict__ out)
{
    float m = 0.0f;
    for (int i = blockIdx.x * 256 + threadIdx.x; i < n; i += gridDim.x * 256)
        m = fmaxf(m, fabsf(x[i]));
#pragma unroll
    for (int off = 16; off >= 1; off >>= 1)
        m = fmaxf(m, __shfl_xor_sync(0xffffffffu, m, off));
    if ((threadIdx.x & 31) == 0)
        atomicMax(out, __float_as_uint(m));
}

// ---------------------------------------------------------------------------
// quantize attn fp32 -> digit planes
// ---------------------------------------------------------------------------
__global__ __launch_bounds__(256)
void quant_attn_kernel(const float* __restrict__ x,
                       int8_t* __restrict__ d1, int8_t* __restrict__ d2, int n)
{
    const float maxv = fmaxf(__uint_as_float(g_maxA), 1e-30f);
    const float S = 32512.0f / maxv;
    int i = blockIdx.x * 256 + threadIdx.x;
    if (i < n) quant2(x[i], S, d1[i], d2[i]);
}

// ---------------------------------------------------------------------------
// transpose + quantize  W[K][N] -> digit planes [N][K]
// ---------------------------------------------------------------------------
__global__ __launch_bounds__(256)
void transpose_quant_kernel(const float* __restrict__ W,
                            int8_t* __restrict__ d1, int8_t* __restrict__ d2,
                            int K, int N)
{
    __shared__ float s[64][33];
    const int tid = threadIdx.x;
    const int k0 = blockIdx.y * 64;
    const int n0 = blockIdx.x * 32;
    const float maxv = fmaxf(__uint_as_float(g_maxW), 1e-30f);
    const float S = 32512.0f / maxv;

#pragma unroll
    for (int i = 0; i < 8; i++) {
        int idx = tid + i * 256;
        int nl = idx & 31;
        int kl = idx >> 5;
        s[kl][nl] = W[(size_t)(k0 + kl) * N + n0 + nl];
    }
    __syncthreads();

#pragma unroll
    for (int i = 0; i < 8; i++) {
        int idx = tid + i * 256;
        int kl = idx & 63;
        int nl = idx >> 6;
        size_t o = (size_t)(n0 + nl) * K + k0 + kl;
        quant2(s[kl][nl], S, d1[o], d2[o]);
    }
}

// ---------------------------------------------------------------------------
// bf16x3 GEMM + bias (R11 verbatim, at the HMMA cap)
// mode 0: fp32 C. mode 1: split bf16 planes Chi/Clo.
// ---------------------------------------------------------------------------
#define GASTR 12
#define GBSTR 136

__global__ __launch_bounds__(256)
void gemm_bf16x3(const float* __restrict__ A, const float* __restrict__ B,
                 const float* __restrict__ bias,
                 float* __restrict__ Cf,
                 uint32_t* __restrict__ Chi, uint32_t* __restrict__ Clo,
                 int M, int N, int K, int mode)
{
    __shared__ uint32_t Ah[2][128 * GASTR], Al[2][128 * GASTR];
    __shared__ uint32_t Bh[2][8 * GBSTR],  Bl[2][8 * GBSTR];

    const int tid  = threadIdx.x;
    const int warp = tid >> 5;
    const int lane = tid & 31;
    const int g = lane >> 2;
    const int t = lane & 3;
    const int wm = (warp >> 2) * 64;
    const int wn = (warp & 3) * 32;
    const int brow = blockIdx.y * 128;
    const int bcol = blockIdx.x * 128;

    float acc[4][4][4];
#pragma unroll
    for (int mt = 0; mt < 4; mt++)
#pragma unroll
        for (int nt = 0; nt < 4; nt++)
#pragma unroll
            for (int r = 0; r < 4; r++) acc[mt][nt][r] = 0.0f;

    const int am[2] = { (tid + 0) >> 2, (tid + 256) >> 2 };
    const int aq[2] = { (tid + 0) & 3,  (tid + 256) & 3 };
    const int bkp   = tid >> 5;
    const int bn0   = (tid & 31) * 4;

    float4 pa[2], pb0, pb1;

    auto prefetch = [&](int k0) {
#pragma unroll
        for (int it = 0; it < 2; it++)
            pa[it] = *(const float4*)(A + (size_t)(brow + am[it]) * K + k0 + aq[it] * 4);
        pb0 = *(const float4*)(B + (size_t)(k0 + 2 * bkp) * N + bcol + bn0);
        pb1 = *(const float4*)(B + (size_t)(k0 + 2 * bkp + 1) * N + bcol + bn0);
    };
    auto stage = [&](int buf) {
#pragma unroll
        for (int it = 0; it < 2; it++) {
            uint32_t h0, l0, h1, l1;
            split2(pa[it].x, pa[it].y, h0, l0);
            split2(pa[it].z, pa[it].w, h1, l1);
            int base = am[it] * GASTR + aq[it] * 2;
            Ah[buf][base] = h0;  Ah[buf][base + 1] = h1;
            Al[buf][base] = l0;  Al[buf][base + 1] = l1;
        }
        uint32_t h[4], l[4];
        split2(pb0.x, pb1.x, h[0], l[0]);
        split2(pb0.y, pb1.y, h[1], l[1]);
        split2(pb0.z, pb1.z, h[2], l[2]);
        split2(pb0.w, pb1.w, h[3], l[3]);
        *(uint4*)&Bh[buf][bkp * GBSTR + bn0] = make_uint4(h[0], h[1], h[2], h[3]);
        *(uint4*)&Bl[buf][bkp * GBSTR + bn0] = make_uint4(l[0], l[1], l[2], l[3]);
    };

    prefetch(0);
    stage(0);
    __syncthreads();

    int buf = 0;
    for (int k0 = 0; k0 < K; k0 += 16) {
        const bool has_next = (k0 + 16) < K;
        if (has_next) prefetch(k0 + 16);

        uint32_t bh[4][2], bl[4][2];
#pragma unroll
        for (int nt = 0; nt < 4; nt++) {
            const int col = wn + nt * 8 + g;
            bh[nt][0] = Bh[buf][t * GBSTR + col];
            bh[nt][1] = Bh[buf][(t + 4) * GBSTR + col];
            bl[nt][0] = Bl[buf][t * GBSTR + col];
            bl[nt][1] = Bl[buf][(t + 4) * GBSTR + col];
        }
#pragma unroll
        for (int mt = 0; mt < 4; mt++) {
            const int r = wm + mt * 16 + g;
            uint32_t ah0 = Ah[buf][r * GASTR + t];
            uint32_t ah1 = Ah[buf][(r + 8) * GASTR + t];
            uint32_t ah2 = Ah[buf][r * GASTR + t + 4];
            uint32_t ah3 = Ah[buf][(r + 8) * GASTR + t + 4];
            uint32_t al0 = Al[buf][r * GASTR + t];
            uint32_t al1 = Al[buf][(r + 8) * GASTR + t];
            uint32_t al2 = Al[buf][r * GASTR + t + 4];
            uint32_t al3 = Al[buf][(r + 8) * GASTR + t + 4];
#pragma unroll
            for (int nt = 0; nt < 4; nt++) {
                mma_bf16(acc[mt][nt], ah0, ah1, ah2, ah3, bh[nt][0], bh[nt][1]);
                mma_bf16(acc[mt][nt], ah0, ah1, ah2, ah3, bl[nt][0], bl[nt][1]);
                mma_bf16(acc[mt][nt], al0, al1, al2, al3, bh[nt][0], bh[nt][1]);
            }
        }

        if (has_next) {
            stage(buf ^ 1);
            __syncthreads();
            buf ^= 1;
        }
    }

#pragma unroll
    for (int nt = 0; nt < 4; nt++) {
        const int col = bcol + wn + nt * 8 + 2 * t;
        const float2 bv = *(const float2*)(bias + col);
#pragma unroll
        for (int mt = 0; mt < 4; mt++) {
            const int row0 = brow + wm + mt * 16 + g;
            float v00 = acc[mt][nt][0] + bv.x, v01 = acc[mt][nt][1] + bv.y;
            float v10 = acc[mt][nt][2] + bv.x, v11 = acc[mt][nt][3] + bv.y;
            if (mode == 0) {
                *(float2*)(Cf + (size_t)row0 * N + col)       = make_float2(v00, v01);
                *(float2*)(Cf + (size_t)(row0 + 8) * N + col) = make_float2(v10, v11);
            } else {
                uint32_t h, l;
                size_t i0 = ((size_t)row0 * N + col) >> 1;
                split2(v00, v01, h, l);  Chi[i0] = h;  Clo[i0] = l;
                size_t i1 = ((size_t)(row0 + 8) * N + col) >> 1;
                split2(v10, v11, h, l);  Chi[i1] = h;  Clo[i1] = l;
            }
        }
    }
}

// ---------------------------------------------------------------------------
// V projection GEMM (fp16 2-term): V = hidden @ Wv + bias_v
// A single fp16, B fp16 hi/lo pair -> 2 MMA per tile. Dedicated kernel,
// monomorphic inner loop. Writes fp16 planes into qkv col range [2048,3072).
// Chi/Clo are passed pre-offset (qh + 1024 u32); plane row stride LD32.
// ---------------------------------------------------------------------------
__global__ __launch_bounds__(256)
void gemm_v_f16(const float* __restrict__ A, const float* __restrict__ B,
                const float* __restrict__ bias,
                uint32_t* __restrict__ Chi, uint32_t* __restrict__ Clo,
                int M, int N, int K)
{
    __shared__ uint32_t Ah[2][128 * GASTR];
    __shared__ uint32_t Bh[2][8 * GBSTR], Bl[2][8 * GBSTR];

    const int tid  = threadIdx.x;
    const int warp = tid >> 5;
    const int lane = tid & 31;
    const int g = lane >> 2;
    const int t = lane & 3;
    const int wm = (warp >> 2) * 64;
    const int wn = (warp & 3) * 32;
    const int brow = blockIdx.y * 128;
    const int bcol = blockIdx.x * 128;     // within Wv's N=1024

    float acc[4][4][4];
#pragma unroll
    for (int mt = 0; mt < 4; mt++)
#pragma unroll
        for (int nt = 0; nt < 4; nt++)
#pragma unroll
            for (int r = 0; r < 4; r++) acc[mt][nt][r] = 0.0f;

    const int am[2] = { (tid + 0) >> 2, (tid + 256) >> 2 };
    const int aq[2] = { (tid + 0) & 3,  (tid + 256) & 3 };
    const int bkp   = tid >> 5;
    const int bn0   = (tid & 31) * 4;

    float4 pa[2], pb0, pb1;

    auto prefetch = [&](int k0) {
#pragma unroll
        for (int it = 0; it < 2; it++)
            pa[it] = *(const float4*)(A + (size_t)(brow + am[it]) * K + k0 + aq[it] * 4);
        pb0 = *(const float4*)(B + (size_t)(k0 + 2 * bkp) * N + bcol + bn0);
        pb1 = *(const float4*)(B + (size_t)(k0 + 2 * bkp + 1) * N + bcol + bn0);
    };
    auto stage = [&](int buf) {
#pragma unroll
        for (int it = 0; it < 2; it++) {
            int base = am[it] * GASTR + aq[it] * 2;
            Ah[buf][base]     = pack_h2(pa[it].x, pa[it].y);
            Ah[buf][base + 1] = pack_h2(pa[it].z, pa[it].w);
        }
        uint32_t h[4], l[4];
        split2h(pb0.x, pb1.x, h[0], l[0]);
        split2h(pb0.y, pb1.y, h[1], l[1]);
        split2h(pb0.z, pb1.z, h[2], l[2]);
        split2h(pb0.w, pb1.w, h[3], l[3]);
        *(uint4*)&Bh[buf][bkp * GBSTR + bn0] = make_uint4(h[0], h[1], h[2], h[3]);
        *(uint4*)&Bl[buf][bkp * GBSTR + bn0] = make_uint4(l[0], l[1], l[2], l[3]);
    };

    prefetch(0);
    stage(0);
    __syncthreads();

    int buf = 0;
    for (int k0 = 0; k0 < K; k0 += 16) {
        const bool has_next = (k0 + 16) < K;
        if (has_next) prefetch(k0 + 16);

        uint32_t bh[4][2], bl[4][2];
#pragma unroll
        for (int nt = 0; nt < 4; nt++) {
            const int col = wn + nt * 8 + g;
            bh[nt][0] = Bh[buf][t * GBSTR + col];
            bh[nt][1] = Bh[buf][(t + 4) * GBSTR + col];
            bl[nt][0] = Bl[buf][t * GBSTR + col];
            bl[nt][1] = Bl[buf][(t + 4) * GBSTR + col];
        }
#pragma unroll
        for (int mt = 0; mt < 4; mt++) {
            const int r = wm + mt * 16 + g;
            uint32_t a0 = Ah[buf][r * GASTR + t];
            uint32_t a1 = Ah[buf][(r + 8) * GASTR + t];
            uint32_t a2 = Ah[buf][r * GASTR + t + 4];
            uint32_t a3 = Ah[buf][(r + 8) * GASTR + t + 4];
#pragma unroll
            for (int nt = 0; nt < 4; nt++) {
                mma_f16(acc[mt][nt], a0, a1, a2, a3, bh[nt][0], bh[nt][1]);
                mma_f16(acc[mt][nt], a0, a1, a2, a3, bl[nt][0], bl[nt][1]);
            }
        }

        if (has_next) {
            stage(buf ^ 1);
            __syncthreads();
            buf ^= 1;
        }
    }

#pragma unroll
    for (int nt = 0; nt < 4; nt++) {
        const int col = bcol + wn + nt * 8 + 2 * t;   // within N=1024
        const float2 bv = *(const float2*)(bias + col);
#pragma unroll
        for (int mt = 0; mt < 4; mt++) {
            const int row0 = brow + wm + mt * 16 + g;
            uint32_t h, l;
            size_t i0 = (size_t)row0 * LD32 + (col >> 1);
            split2h(acc[mt][nt][0] + bv.x, acc[mt][nt][1] + bv.y, h, l);
            Chi[i0] = h;  Clo[i0] = l;
            size_t i1 = (size_t)(row0 + 8) * LD32 + (col >> 1);
            split2h(acc[mt][nt][2] + bv.x, acc[mt][nt][3] + bv.y, h, l);
            Chi[i1] = h;  Clo[i1] = l;
        }
    }
}

// ---------------------------------------------------------------------------
// Flash attention v4 (R11/R12 verbatim): QK^T bf16x3, PV fp16 2-term,
// fused block-level max|attn|.
// ---------------------------------------------------------------------------
#define FSTR 36
#define OFF_QL (128 * FSTR)
#define OFF_BUF (2 * 128 * FSTR)
#define BUF_SZ  (4 * 64 * FSTR)
#define PL_SZ   (64 * FSTR)
#define FL_SMEM ((OFF_BUF + 2 * BUF_SZ) * 4)   // 110592 bytes

__global__ __launch_bounds__(256, 2)
void flash_bf16x3(const uint32_t* __restrict__ qh,
                  const uint32_t* __restrict__ ql,
                  float* __restrict__ out)
{
    extern __shared__ uint32_t sm[];
    uint32_t* Qh = sm;
    uint32_t* Ql = sm + OFF_QL;
    const uint32_t sb = (uint32_t)__cvta_generic_to_shared(sm);

    const int qbx = gridDim.x - 1 - blockIdx.x;
    const int h   = blockIdx.y;
    const int b   = blockIdx.z;

    const int tid  = threadIdx.x;
    const int wid  = tid >> 5;
    const int lane = tid & 31;
    const int g = lane >> 2;
    const int t = lane & 3;

    const int qoff = h * 32;
    const int koff = 512 + h * 32;
    const int voff = 1024 + h * 32;

    const int wq = qbx * 128 + wid * 16;

#pragma unroll
    for (int it = 0; it < 16; it++) {
        int idx = tid + it * 256;
        int row = idx >> 5;
        int dp  = idx & 31;
        size_t gi = (size_t)(b * SEQ + qbx * 128 + row) * LD32 + qoff + dp;
        Qh[row * FSTR + dp] = qh[gi];
        Ql[row * FSTR + dp] = ql[gi];
    }

    const int crow = tid >> 3;
    const int cch  = tid & 7;
    auto issue_blk = [&](int jb, int buf) {
        const uint32_t base = sb + (uint32_t)((OFF_BUF + buf * BUF_SZ) * 4);
        const size_t trow = (size_t)(b * SEQ + jb * 64);
#pragma unroll
        for (int i = 0; i < 2; i++) {
            int row = crow + i * 32;
            uint32_t so = (uint32_t)(row * 144 + cch * 16);
            size_t gr = (trow + row) * LD32 + cch * 4;
            cp16(base + 0 * (PL_SZ * 4) + so, qh + gr + koff);
            cp16(base + 1 * (PL_SZ * 4) + so, ql + gr + koff);
            cp16(base + 2 * (PL_SZ * 4) + so, qh + gr + voff);
            cp16(base + 3 * (PL_SZ * 4) + so, ql + gr + voff);
        }
        CP_COMMIT();
    };

    const uint32_t qa   = sb + (uint32_t)((wid * 16 + (lane & 15)) * 144 +
                                          (lane >> 4) * 16);
    const uint32_t krow = (uint32_t)((lane & 7) + ((lane >> 4) & 1) * 8);
    const uint32_t kcol = (uint32_t)(((lane >> 3) & 1) * 16);
    const uint32_t vrow = (uint32_t)(lane & 15);
    const uint32_t vcol = (uint32_t)(((lane >> 4) & 1) * 16);

    float oa[8][4];
#pragma unroll
    for (int nt = 0; nt < 8; nt++)
#pragma unroll
        for (int r = 0; r < 4; r++) oa[nt][r] = 0.0f;
    float m0 = -1e30f, m1 = -1e30f, l0 = 0.0f, l1 = 0.0f;

    const int r0g = wq + g;
    const int r1g = wq + g + 8;
    const int nblocks = 2 * qbx + 2;

    issue_blk(0, 0);
    issue_blk(1, 1);

    for (int jb = 0; jb < nblocks; jb++) {
        if (jb + 1 < nblocks) CP_WAIT(1); else CP_WAIT(0);
        __syncthreads();

        if (jb * 64 <= wq + 15) {
            const uint32_t kbH = sb + (uint32_t)((OFF_BUF + (jb & 1) * BUF_SZ) * 4);
            const uint32_t kbL = kbH + PL_SZ * 4;
            const uint32_t vbH = kbL + PL_SZ * 4;
            const uint32_t vbL = vbH + PL_SZ * 4;

            float sc[8][4];
#pragma unroll
            for (int nt = 0; nt < 8; nt++)
#pragma unroll
                for (int r = 0; r < 4; r++) sc[nt][r] = 0.0f;

#pragma unroll
            for (int s = 0; s < 4; s++) {
                uint32_t q0, q1, q2, q3, p0, p1, p2, p3;
                ldsm4(q0, q1, q2, q3, qa + (uint32_t)(s * 32));
                ldsm4(p0, p1, p2, p3, qa + (uint32_t)(OFF_QL * 4 + s * 32));
#pragma unroll
                for (int np = 0; np < 4; np++) {
                    const uint32_t ro = (uint32_t)((np * 16 + krow) * 144) +
                                        (uint32_t)(s * 32) + kcol;
                    uint32_t kh0, kh1, kh2, kh3, kl0, kl1, kl2, kl3;
                    ldsm4(kh0, kh1, kh2, kh3, kbH + ro);
                    ldsm4(kl0, kl1, kl2, kl3, kbL + ro);
                    mma_bf16(sc[2 * np],     q0, q1, q2, q3, kh0, kh1);
                    mma_bf16(sc[2 * np],     q0, q1, q2, q3, kl0, kl1);
                    mma_bf16(sc[2 * np],     p0, p1, p2, p3, kh0, kh1);
                    mma_bf16(sc[2 * np + 1], q0, q1, q2, q3, kh2, kh3);
                    mma_bf16(sc[2 * np + 1], q0, q1, q2, q3, kl2, kl3);
                    mma_bf16(sc[2 * np + 1], p0, p1, p2, p3, kh2, kh3);
                }
            }

            if (jb * 64 + 63 > wq) {
#pragma unroll
                for (int nt = 0; nt < 8; nt++) {
                    int c = jb * 64 + nt * 8 + 2 * t;
                    if (c > r0g)     sc[nt][0] = -1e30f;
                    if (c + 1 > r0g) sc[nt][1] = -1e30f;
                    if (c > r1g)     sc[nt][2] = -1e30f;
                    if (c + 1 > r1g) sc[nt][3] = -1e30f;
                }
            }

            float mx0 = -1e30f, mx1 = -1e30f;
#pragma unroll
            for (int nt = 0; nt < 8; nt++) {
                mx0 = fmaxf(mx0, fmaxf(sc[nt][0], sc[nt][1]));
                mx1 = fmaxf(mx1, fmaxf(sc[nt][2], sc[nt][3]));
            }
#pragma unroll
            for (int off = 1; off <= 2; off <<= 1) {
                mx0 = fmaxf(mx0, __shfl_xor_sync(0xffffffffu, mx0, off));
                mx1 = fmaxf(mx1, __shfl_xor_sync(0xffffffffu, mx1, off));
            }
            float mn0 = fmaxf(m0, mx0), mn1 = fmaxf(m1, mx1);
            float corr0 = __expf(m0 - mn0), corr1 = __expf(m1 - mn1);
            float s0 = 0.0f, s1 = 0.0f;
#pragma unroll
            for (int nt = 0; nt < 8; nt++) {
                sc[nt][0] = __expf(sc[nt][0] - mn0);
                sc[nt][1] = __expf(sc[nt][1] - mn0);
                sc[nt][2] = __expf(sc[nt][2] - mn1);
                sc[nt][3] = __expf(sc[nt][3] - mn1);
                s0 += sc[nt][0] + sc[nt][1];
                s1 += sc[nt][2] + sc[nt][3];
            }
#pragma unroll
            for (int off = 1; off <= 2; off <<= 1) {
                s0 += __shfl_xor_sync(0xffffffffu, s0, off);
                s1 += __shfl_xor_sync(0xffffffffu, s1, off);
            }
            l0 = l0 * corr0 + s0;  m0 = mn0;
            l1 = l1 * corr1 + s1;  m1 = mn1;
#pragma unroll
            for (int nt = 0; nt < 8; nt++) {
                oa[nt][0] *= corr0;  oa[nt][1] *= corr0;
                oa[nt][2] *= corr1;  oa[nt][3] *= corr1;
            }

#pragma unroll
            for (int s = 0; s < 4; s++) {
                uint32_t ph[4];
                ph[0] = pack_h2(sc[2 * s][0],     sc[2 * s][1]);
                ph[1] = pack_h2(sc[2 * s][2],     sc[2 * s][3]);
                ph[2] = pack_h2(sc[2 * s + 1][0], sc[2 * s + 1][1]);
                ph[3] = pack_h2(sc[2 * s + 1][2], sc[2 * s + 1][3]);
#pragma unroll
                for (int np = 0; np < 4; np++) {
                    const uint32_t ro = (uint32_t)((s * 16 + vrow) * 144) +
                                        (uint32_t)(np * 32) + vcol;
                    uint32_t vh0, vh1, vh2, vh3, vl0, vl1, vl2, vl3;
                    ldsm4t(vh0, vh1, vh2, vh3, vbH + ro);
                    ldsm4t(vl0, vl1, vl2, vl3, vbL + ro);
                    mma_f16(oa[2 * np],     ph[0], ph[1], ph[2], ph[3], vh0, vh1);
                    mma_f16(oa[2 * np],     ph[0], ph[1], ph[2], ph[3], vl0, vl1);
                    mma_f16(oa[2 * np + 1], ph[0], ph[1], ph[2], ph[3], vh2, vh3);
                    mma_f16(oa[2 * np + 1], ph[0], ph[1], ph[2], ph[3], vl2, vl3);
                }
            }
        }

        __syncthreads();
        if (jb + 2 < nblocks) issue_blk(jb + 2, jb & 1);
    }

    // epilogue: store + block-level max|attn|
    const float inv0 = 1.0f / l0, inv1 = 1.0f / l1;
    const size_t orow0 = (size_t)(b * SEQ + r0g) * HIDDEN + h * HDIM;
    const size_t orow1 = (size_t)(b * SEQ + r1g) * HIDDEN + h * HDIM;
    float lmax = 0.0f;
#pragma unroll
    for (int nt = 0; nt < 8; nt++) {
        const int d = nt * 8 + 2 * t;
        float2 o0 = make_float2(oa[nt][0] * inv0, oa[nt][1] * inv0);
        float2 o1 = make_float2(oa[nt][2] * inv1, oa[nt][3] * inv1);
        *(float2*)(out + orow0 + d) = o0;
        *(float2*)(out + orow1 + d) = o1;
        lmax = fmaxf(lmax, fmaxf(fmaxf(fabsf(o0.x), fabsf(o0.y)),
                                 fmaxf(fabsf(o1.x), fabsf(o1.y))));
    }
#pragma unroll
    for (int off = 16; off >= 1; off >>= 1)
        lmax = fmaxf(lmax, __shfl_xor_sync(0xffffffffu, lmax, off));
    __syncthreads();
    float* red = (float*)sm;
    if (lane == 0) red[wid] = lmax;
    __syncthreads();
    if (tid == 0) {
        float bm = red[0];
#pragma unroll
        for (int w = 1; w < 8; w++) bm = fmaxf(bm, red[w]);
        atomicMax(&g_maxA, __float_as_uint(bm));
    }
}

// ---------------------------------------------------------------------------
// int8 2-digit GEMM + bias (verbatim)
// ---------------------------------------------------------------------------
#define IA_PL 6144
#define IB_PL 3072
#define ISTG (2 * IA_PL + 2 * IB_PL)
#define INST 4
#define INT8_SMEM (INST * ISTG)      // 73728

__global__ __launch_bounds__(256, 2)
void gemm_int8(const int8_t* __restrict__ A1, const int8_t* __restrict__ A2,
               const int8_t* __restrict__ W1, const int8_t* __restrict__ W2,
               const float* __restrict__ bias, float* __restrict__ C,
               int M, int N, int K)
{
    extern __shared__ uint32_t smem[];
    const uint32_t sb = (uint32_t)__cvta_generic_to_shared(smem);

    const int tid  = threadIdx.x;
    const int warp = tid >> 5;
    const int lane = tid & 31;
    const int g = lane >> 2;
    const int t = lane & 3;
    const int wm = (warp >> 1) * 32;
    const int wn = (warp & 1) * 32;
    const int brow = blockIdx.y * 128;
    const int bcol = blockIdx.x * 64;

    const int arow = tid >> 1, ahalf = tid & 1;
    const int wrow = tid >> 2, whalf = (tid >> 1) & 1, wpl = tid & 1;
    const int8_t* gA[2] = { A1 + (size_t)(brow + arow) * K + ahalf * 16,
                            A2 + (size_t)(brow + arow) * K + ahalf * 16 };
    const int8_t* gW   = (wpl ? W2 : W1) + (size_t)(bcol + wrow) * K + whalf * 16;

    auto issue_chunk = [&](int c) {
        const uint32_t base = sb + (uint32_t)((c & (INST - 1)) * ISTG);
        const int k0 = c * 32;
        cp16(base + 0 * IA_PL + arow * 48 + ahalf * 16, gA[0] + k0);
        cp16(base + 1 * IA_PL + arow * 48 + ahalf * 16, gA[1] + k0);
        cp16(base + 2 * IA_PL + wpl * IB_PL + wrow * 48 + whalf * 16, gW + k0);
        CP_COMMIT();
    };

    const int laA = (lane & 7) + ((lane >> 3) & 1) * 8;
    const uint32_t kaA = (uint32_t)(((lane >> 4) & 1) * 16);
    const int laB = (lane & 7) + ((lane >> 4) & 1) * 8;
    const uint32_t kaB = (uint32_t)(((lane >> 3) & 1) * 16);

    int acc1[2][4][4], acc2[2][4][4];
#pragma unroll
    for (int mt = 0; mt < 2; mt++)
#pragma unroll
        for (int nt = 0; nt < 4; nt++)
#pragma unroll
            for (int r = 0; r < 4; r++) { acc1[mt][nt][r] = 0; acc2[mt][nt][r] = 0; }

    const int NC = K / 32;
#pragma unroll
    for (int s = 0; s < INST - 1; s++) issue_chunk(s);

    for (int c = 0; c < NC; c++) {
        CP_WAIT(INST - 2);
        __syncthreads();
        if (c + INST - 1 < NC) issue_chunk(c + INST - 1);

        const uint32_t base = sb + (uint32_t)((c & (INST - 1)) * ISTG);
        uint32_t b1[4][2], b2[4][2];
#pragma unroll
        for (int np = 0; np < 2; np++) {
            const uint32_t ro = (uint32_t)((wn + np * 16 + laB) * 48) + kaB;
            ldsm4(b1[2 * np][0], b1[2 * np][1], b1[2 * np + 1][0], b1[2 * np + 1][1],
                  base + 2 * IA_PL + ro);
            ldsm4(b2[2 * np][0], b2[2 * np][1], b2[2 * np + 1][0], b2[2 * np + 1][1],
                  base + 2 * IA_PL + IB_PL + ro);
        }
#pragma unroll
        for (int mt = 0; mt < 2; mt++) {
            const uint32_t ro = (uint32_t)((wm + mt * 16 + laA) * 48) + kaA;
            uint32_t a1f[4], a2f[4];
            ldsm4(a1f[0], a1f[1], a1f[2], a1f[3], base + ro);
            ldsm4(a2f[0], a2f[1], a2f[2], a2f[3], base + IA_PL + ro);
#pragma unroll
            for (int nt = 0; nt < 4; nt++) {
                mma_s8(acc1[mt][nt], a1f[0], a1f[1], a1f[2], a1f[3],
                       b1[nt][0], b1[nt][1]);
                mma_s8(acc2[mt][nt], a1f[0], a1f[1], a1f[2], a1f[3],
                       b2[nt][0], b2[nt][1]);
                mma_s8(acc2[mt][nt], a2f[0], a2f[1], a2f[2], a2f[3],
                       b1[nt][0], b1[nt][1]);
            }
        }
    }

    const float maxA = fmaxf(__uint_as_float(g_maxA), 1e-30f);
    const float maxW = fmaxf(__uint_as_float(g_maxW), 1e-30f);
    const float inv = (maxA * maxW) / (32512.0f * 32512.0f);

#pragma unroll
    for (int nt = 0; nt < 4; nt++) {
        const int col = bcol + wn + nt * 8 + 2 * t;
        const float2 bv = *(const float2*)(bias + col);
#pragma unroll
        for (int mt = 0; mt < 2; mt++) {
            const int row0 = brow + wm + mt * 16 + g;
            float2 o0, o1;
            o0.x = (65536.0f * (float)acc1[mt][nt][0] + 256.0f * (float)acc2[mt][nt][0]) * inv + bv.x;
            o0.y = (65536.0f * (float)acc1[mt][nt][1] + 256.0f * (float)acc2[mt][nt][1]) * inv + bv.y;
            o1.x = (65536.0f * (float)acc1[mt][nt][2] + 256.0f * (float)acc2[mt][nt][2]) * inv + bv.x;
            o1.y = (65536.0f * (float)acc1[mt][nt][3] + 256.0f * (float)acc2[mt][nt][3]) * inv + bv.y;
            *(float2*)(C + (size_t)row0 * N + col)       = o0;
            *(float2*)(C + (size_t)(row0 + 8) * N + col) = o1;
        }
    }
}

// ---------------------------------------------------------------------------
// Launch
// ---------------------------------------------------------------------------
extern "C" void kernel_launch(void* const* d_in, const int* in_sizes, int n_in,
                              void* d_out, int out_size)
{
    const float* hidden = (const float*)d_in[0];
    const float* w_attn = (const float*)d_in[1];
    const float* b_attn = (const float*)d_in[2];
    const float* w_proj = (const float*)d_in[3];
    const float* b_proj = (const float*)d_in[4];
    float* out = (float*)d_out;

    uint32_t *qh, *ql;
    float* attn;
    int8_t *a1, *a2, *w1, *w2;
    unsigned* mW;
    cudaGetSymbolAddress((void**)&qh, g_qh);
    cudaGetSymbolAddress((void**)&ql, g_ql);
    cudaGetSymbolAddress((void**)&attn, g_attn);
    cudaGetSymbolAddress((void**)&a1, g_a1);
    cudaGetSymbolAddress((void**)&a2, g_a2);
    cudaGetSymbolAddress((void**)&w1, g_w1);
    cudaGetSymbolAddress((void**)&w2, g_w2);
    cudaGetSymbolAddress((void**)&mW, g_maxW);

    static bool attr_set = false;
    if (!attr_set) {
        cudaFuncSetAttribute(flash_bf16x3,
                             cudaFuncAttributeMaxDynamicSharedMemorySize, FL_SMEM);
        cudaFuncSetAttribute(gemm_int8,
                             cudaFuncAttributeMaxDynamicSharedMemorySize, INT8_SMEM);
        attr_set = true;
    }

    // 0) w_proj max + transpose/quantize
    maxabs_kernel<<<256, 256>>>(w_proj, HIDDEN * HIDDEN, mW);
    {
        dim3 gp(HIDDEN / 32, HIDDEN / 64);
        transpose_quant_kernel<<<gp, 256>>>(w_proj, w1, w2, HIDDEN, HIDDEN);
    }
    // 1a) Q/K projection (bf16x3, cols 0..2048)
    {
        dim3 grid((2 * HIDDEN) / 128, M_TOK / 128);
        gemm_bf16x3<<<grid, 256>>>(hidden, w_attn, b_attn,
                                   nullptr, qh, ql,
                                   M_TOK, QKV_N, HIDDEN, 1);
    }
    // 1b) V projection (fp16 2-term, cols 2048..3072) -> fp16 planes
    {
        dim3 grid(HIDDEN / 128, M_TOK / 128);
        gemm_v_f16<<<grid, 256>>>(hidden, w_attn + 2 * HIDDEN,
                                  b_attn + 2 * HIDDEN,
                                  qh + 1024, ql + 1024,
                                  M_TOK, QKV_N, HIDDEN);
    }
    // 2) flash attention v4 -> fp32 attn + g_maxA
    {
        dim3 grid(SEQ / 128, NHEAD, BATCH);
        flash_bf16x3<<<grid, 256, FL_SMEM>>>(qh, ql, attn);
    }
    // 3) quantize attn to int8 digits
    {
        const int n = M_TOK * HIDDEN;
        quant_attn_kernel<<<(n + 255) / 256, 256>>>(attn, a1, a2, n);
    }
    // 4) output projection via int8 IMMA
    {
        dim3 grid(HIDDEN / 64, M_TOK / 128);
        gemm_int8<<<grid, 256, INT8_SMEM>>>(a1, a2, w1, w2, b_proj, out,
                                            M_TOK, HIDDEN, HIDDEN);
    }
}

// round 16
// speedup vs baseline: 1.0531x; 1.0531x over previous
#include <cuda_runtime.h>
#include <cuda_bf16.h>
#include <cuda_fp16.h>
#include <math.h>
#include <stdint.h>

// ---------------------------------------------------------------------------
// Problem constants
// ---------------------------------------------------------------------------
#define BATCH 2
#define SEQ 2048
#define HIDDEN 1024
#define NHEAD 16
#define HDIM 64
#define M_TOK (BATCH * SEQ)          // 4096
#define QKV_N (3 * HIDDEN)           // 3072
#define LD32 (QKV_N / 2)             // 1536 u32 per token row (qkv planes)

// Scratch (__device__ globals per allocation rules)
__device__ uint32_t g_qh[(size_t)M_TOK * LD32];      // qkv hi plane (V range: fp16)
__device__ uint32_t g_ql[(size_t)M_TOK * LD32];      // qkv lo plane
__device__ float    g_attn[(size_t)M_TOK * HIDDEN];  // attention output fp32
__device__ int8_t   g_a1[(size_t)M_TOK * HIDDEN];    // attn digit1
__device__ int8_t   g_a2[(size_t)M_TOK * HIDDEN];    // attn digit2
__device__ int8_t   g_w1[(size_t)HIDDEN * HIDDEN];   // w_proj^T digit1 [n][k]
__device__ int8_t   g_w2[(size_t)HIDDEN * HIDDEN];   // w_proj^T digit2
__device__ unsigned g_maxA;                          // max|attn| (float bits)
__device__ unsigned g_maxW;                          // max|w_proj|

// ---------------------------------------------------------------------------
// Helpers
// ---------------------------------------------------------------------------
__device__ __forceinline__ void split2(float x, float y,
                                       uint32_t& hi, uint32_t& lo) {
    __nv_bfloat162 h = __floats2bfloat162_rn(x, y);
    float2 hf = __bfloat1622float2(h);
    __nv_bfloat162 l = __floats2bfloat162_rn(x - hf.x, y - hf.y);
    hi = *reinterpret_cast<uint32_t*>(&h);
    lo = *reinterpret_cast<uint32_t*>(&l);
}

// fp16 hi/lo split (pair reproduces fp32 to ~2^-23)
__device__ __forceinline__ void split2h(float x, float y,
                                        uint32_t& hi, uint32_t& lo) {
    __half2 h = __floats2half2_rn(x, y);
    float2 hf = __half22float2(h);
    __half2 l = __floats2half2_rn(x - hf.x, y - hf.y);
    hi = *reinterpret_cast<uint32_t*>(&h);
    lo = *reinterpret_cast<uint32_t*>(&l);
}

__device__ __forceinline__ uint32_t pack_h2(float x, float y) {
    __half2 h = __floats2half2_rn(x, y);
    return *reinterpret_cast<uint32_t*>(&h);
}

__device__ __forceinline__ void mma_bf16(float* c, uint32_t a0, uint32_t a1,
                                         uint32_t a2, uint32_t a3,
                                         uint32_t b0, uint32_t b1) {
    asm volatile(
        "mma.sync.aligned.m16n8k16.row.col.f32.bf16.bf16.f32 "
        "{%0,%1,%2,%3}, {%4,%5,%6,%7}, {%8,%9}, {%0,%1,%2,%3};"
        : "+f"(c[0]), "+f"(c[1]), "+f"(c[2]), "+f"(c[3])
        : "r"(a0), "r"(a1), "r"(a2), "r"(a3), "r"(b0), "r"(b1));
}

__device__ __forceinline__ void mma_f16(float* c, uint32_t a0, uint32_t a1,
                                        uint32_t a2, uint32_t a3,
                                        uint32_t b0, uint32_t b1) {
    asm volatile(
        "mma.sync.aligned.m16n8k16.row.col.f32.f16.f16.f32 "
        "{%0,%1,%2,%3}, {%4,%5,%6,%7}, {%8,%9}, {%0,%1,%2,%3};"
        : "+f"(c[0]), "+f"(c[1]), "+f"(c[2]), "+f"(c[3])
        : "r"(a0), "r"(a1), "r"(a2), "r"(a3), "r"(b0), "r"(b1));
}

__device__ __forceinline__ void mma_s8(int* c, uint32_t a0, uint32_t a1,
                                       uint32_t a2, uint32_t a3,
                                       uint32_t b0, uint32_t b1) {
    asm volatile(
        "mma.sync.aligned.m16n8k32.row.col.s32.s8.s8.s32 "
        "{%0,%1,%2,%3}, {%4,%5,%6,%7}, {%8,%9}, {%0,%1,%2,%3};"
        : "+r"(c[0]), "+r"(c[1]), "+r"(c[2]), "+r"(c[3])
        : "r"(a0), "r"(a1), "r"(a2), "r"(a3), "r"(b0), "r"(b1));
}

__device__ __forceinline__ void ldsm4(uint32_t& r0, uint32_t& r1,
                                      uint32_t& r2, uint32_t& r3, uint32_t a) {
    asm volatile("ldmatrix.sync.aligned.m8n8.x4.shared.b16 {%0,%1,%2,%3}, [%4];"
                 : "=r"(r0), "=r"(r1), "=r"(r2), "=r"(r3) : "r"(a));
}

__device__ __forceinline__ void ldsm4t(uint32_t& r0, uint32_t& r1,
                                       uint32_t& r2, uint32_t& r3, uint32_t a) {
    asm volatile("ldmatrix.sync.aligned.m8n8.x4.trans.shared.b16 {%0,%1,%2,%3}, [%4];"
                 : "=r"(r0), "=r"(r1), "=r"(r2), "=r"(r3) : "r"(a));
}

__device__ __forceinline__ void cp16(uint32_t smem, const void* gmem) {
    asm volatile("cp.async.ca.shared.global [%0], [%1], 16;"
                 :: "r"(smem), "l"(gmem));
}
#define CP_COMMIT() asm volatile("cp.async.commit_group;" ::: "memory")
#define CP_WAIT(n)  asm volatile("cp.async.wait_group %0;" :: "n"(n) : "memory")

// quantize x (|x| <= max) to q1*256 + q2 with S = 32512/max
__device__ __forceinline__ void quant2(float x, float S, int8_t& d1, int8_t& d2) {
    int q = __float2int_rn(x * S);
    int q1 = (q + 128) >> 8;
    d1 = (int8_t)q1;
    d2 = (int8_t)(q - (q1 << 8));
}

// ---------------------------------------------------------------------------
// max-abs reduction (for w_proj)
// ---------------------------------------------------------------------------
__global__ __launch_bounds__(256)
void maxabs_kernel(const float* __restrict__ x, int n, unsigned* __restrict__ out)
{
    float m = 0.0f;
    for (int i = blockIdx.x * 256 + threadIdx.x; i < n; i += gridDim.x * 256)
        m = fmaxf(m, fabsf(x[i]));
#pragma unroll
    for (int off = 16; off >= 1; off >>= 1)
        m = fmaxf(m, __shfl_xor_sync(0xffffffffu, m, off));
    if ((threadIdx.x & 31) == 0)
        atomicMax(out, __float_as_uint(m));
}

// ---------------------------------------------------------------------------
// quantize attn fp32 -> digit planes (maxA produced by flash epilogue)
// ---------------------------------------------------------------------------
__global__ __launch_bounds__(256)
void quant_attn_kernel(const float* __restrict__ x,
                       int8_t* __restrict__ d1, int8_t* __restrict__ d2, int n)
{
    const float maxv = fmaxf(__uint_as_float(g_maxA), 1e-30f);
    const float S = 32512.0f / maxv;
    int i = blockIdx.x * 256 + threadIdx.x;
    if (i < n) quant2(x[i], S, d1[i], d2[i]);
}

// ---------------------------------------------------------------------------
// transpose + quantize  W[K][N] -> digit planes [N][K]
// ---------------------------------------------------------------------------
__global__ __launch_bounds__(256)
void transpose_quant_kernel(const float* __restrict__ W,
                            int8_t* __restrict__ d1, int8_t* __restrict__ d2,
                            int K, int N)
{
    __shared__ float s[64][33];
    const int tid = threadIdx.x;
    const int k0 = blockIdx.y * 64;
    const int n0 = blockIdx.x * 32;
    const float maxv = fmaxf(__uint_as_float(g_maxW), 1e-30f);
    const float S = 32512.0f / maxv;

#pragma unroll
    for (int i = 0; i < 8; i++) {
        int idx = tid + i * 256;
        int nl = idx & 31;
        int kl = idx >> 5;
        s[kl][nl] = W[(size_t)(k0 + kl) * N + n0 + nl];
    }
    __syncthreads();

#pragma unroll
    for (int i = 0; i < 8; i++) {
        int idx = tid + i * 256;
        int kl = idx & 63;
        int nl = idx >> 6;
        size_t o = (size_t)(n0 + nl) * K + k0 + kl;
        quant2(s[kl][nl], S, d1[o], d2[o]);
    }
}

// ---------------------------------------------------------------------------
// bf16x3 GEMM + bias (at the HMMA cap): C = A[M,K] @ B[K,N] + bias
// mode 0: fp32 C. mode 1: split planes (bf16 for cols<2048, fp16 for V cols).
// ---------------------------------------------------------------------------
#define GASTR 12
#define GBSTR 136

__global__ __launch_bounds__(256)
void gemm_bf16x3(const float* __restrict__ A, const float* __restrict__ B,
                 const float* __restrict__ bias,
                 float* __restrict__ Cf,
                 uint32_t* __restrict__ Chi, uint32_t* __restrict__ Clo,
                 int M, int N, int K, int mode)
{
    __shared__ uint32_t Ah[2][128 * GASTR], Al[2][128 * GASTR];
    __shared__ uint32_t Bh[2][8 * GBSTR],  Bl[2][8 * GBSTR];

    const int tid  = threadIdx.x;
    const int warp = tid >> 5;
    const int lane = tid & 31;
    const int g = lane >> 2;
    const int t = lane & 3;
    const int wm = (warp >> 2) * 64;
    const int wn = (warp & 3) * 32;
    const int brow = blockIdx.y * 128;
    const int bcol = blockIdx.x * 128;

    float acc[4][4][4];
#pragma unroll
    for (int mt = 0; mt < 4; mt++)
#pragma unroll
        for (int nt = 0; nt < 4; nt++)
#pragma unroll
            for (int r = 0; r < 4; r++) acc[mt][nt][r] = 0.0f;

    const int am[2] = { (tid + 0) >> 2, (tid + 256) >> 2 };
    const int aq[2] = { (tid + 0) & 3,  (tid + 256) & 3 };
    const int bkp   = tid >> 5;
    const int bn0   = (tid & 31) * 4;

    float4 pa[2], pb0, pb1;

    auto prefetch = [&](int k0) {
#pragma unroll
        for (int it = 0; it < 2; it++)
            pa[it] = *(const float4*)(A + (size_t)(brow + am[it]) * K + k0 + aq[it] * 4);
        pb0 = *(const float4*)(B + (size_t)(k0 + 2 * bkp) * N + bcol + bn0);
        pb1 = *(const float4*)(B + (size_t)(k0 + 2 * bkp + 1) * N + bcol + bn0);
    };
    auto stage = [&](int buf) {
#pragma unroll
        for (int it = 0; it < 2; it++) {
            uint32_t h0, l0, h1, l1;
            split2(pa[it].x, pa[it].y, h0, l0);
            split2(pa[it].z, pa[it].w, h1, l1);
            int base = am[it] * GASTR + aq[it] * 2;
            Ah[buf][base] = h0;  Ah[buf][base + 1] = h1;
            Al[buf][base] = l0;  Al[buf][base + 1] = l1;
        }
        uint32_t h[4], l[4];
        split2(pb0.x, pb1.x, h[0], l[0]);
        split2(pb0.y, pb1.y, h[1], l[1]);
        split2(pb0.z, pb1.z, h[2], l[2]);
        split2(pb0.w, pb1.w, h[3], l[3]);
        *(uint4*)&Bh[buf][bkp * GBSTR + bn0] = make_uint4(h[0], h[1], h[2], h[3]);
        *(uint4*)&Bl[buf][bkp * GBSTR + bn0] = make_uint4(l[0], l[1], l[2], l[3]);
    };

    prefetch(0);
    stage(0);
    __syncthreads();

    int buf = 0;
    for (int k0 = 0; k0 < K; k0 += 16) {
        const bool has_next = (k0 + 16) < K;
        if (has_next) prefetch(k0 + 16);

        uint32_t bh[4][2], bl[4][2];
#pragma unroll
        for (int nt = 0; nt < 4; nt++) {
            const int col = wn + nt * 8 + g;
            bh[nt][0] = Bh[buf][t * GBSTR + col];
            bh[nt][1] = Bh[buf][(t + 4) * GBSTR + col];
            bl[nt][0] = Bl[buf][t * GBSTR + col];
            bl[nt][1] = Bl[buf][(t + 4) * GBSTR + col];
        }
#pragma unroll
        for (int mt = 0; mt < 4; mt++) {
            const int r = wm + mt * 16 + g;
            uint32_t ah0 = Ah[buf][r * GASTR + t];
            uint32_t ah1 = Ah[buf][(r + 8) * GASTR + t];
            uint32_t ah2 = Ah[buf][r * GASTR + t + 4];
            uint32_t ah3 = Ah[buf][(r + 8) * GASTR + t + 4];
            uint32_t al0 = Al[buf][r * GASTR + t];
            uint32_t al1 = Al[buf][(r + 8) * GASTR + t];
            uint32_t al2 = Al[buf][r * GASTR + t + 4];
            uint32_t al3 = Al[buf][(r + 8) * GASTR + t + 4];
#pragma unroll
            for (int nt = 0; nt < 4; nt++) {
                mma_bf16(acc[mt][nt], ah0, ah1, ah2, ah3, bh[nt][0], bh[nt][1]);
                mma_bf16(acc[mt][nt], ah0, ah1, ah2, ah3, bl[nt][0], bl[nt][1]);
                mma_bf16(acc[mt][nt], al0, al1, al2, al3, bh[nt][0], bh[nt][1]);
            }
        }

        if (has_next) {
            stage(buf ^ 1);
            __syncthreads();
            buf ^= 1;
        }
    }

    const bool vregion = (bcol >= 2 * HIDDEN);   // V columns -> fp16 planes
#pragma unroll
    for (int nt = 0; nt < 4; nt++) {
        const int col = bcol + wn + nt * 8 + 2 * t;
        const float2 bv = *(const float2*)(bias + col);
#pragma unroll
        for (int mt = 0; mt < 4; mt++) {
            const int row0 = brow + wm + mt * 16 + g;
            float v00 = acc[mt][nt][0] + bv.x, v01 = acc[mt][nt][1] + bv.y;
            float v10 = acc[mt][nt][2] + bv.x, v11 = acc[mt][nt][3] + bv.y;
            if (mode == 0) {
                *(float2*)(Cf + (size_t)row0 * N + col)       = make_float2(v00, v01);
                *(float2*)(Cf + (size_t)(row0 + 8) * N + col) = make_float2(v10, v11);
            } else {
                uint32_t h, l;
                size_t i0 = ((size_t)row0 * N + col) >> 1;
                size_t i1 = ((size_t)(row0 + 8) * N + col) >> 1;
                if (vregion) {
                    split2h(v00, v01, h, l);  Chi[i0] = h;  Clo[i0] = l;
                    split2h(v10, v11, h, l);  Chi[i1] = h;  Clo[i1] = l;
                } else {
                    split2(v00, v01, h, l);   Chi[i0] = h;  Clo[i0] = l;
                    split2(v10, v11, h, l);   Chi[i1] = h;  Clo[i1] = l;
                }
            }
        }
    }
}

// ---------------------------------------------------------------------------
// Flash attention v4: QK^T bf16x3, PV fp16 2-term (P single fp16, V fp16 pair).
// Fused block-level max|attn| (one atomic per CTA).
// ---------------------------------------------------------------------------
#define FSTR 36
#define OFF_QL (128 * FSTR)
#define OFF_BUF (2 * 128 * FSTR)
#define BUF_SZ  (4 * 64 * FSTR)
#define PL_SZ   (64 * FSTR)
#define FL_SMEM ((OFF_BUF + 2 * BUF_SZ) * 4)   // 110592 bytes

__global__ __launch_bounds__(256, 2)
void flash_bf16x3(const uint32_t* __restrict__ qh,
                  const uint32_t* __restrict__ ql,
                  float* __restrict__ out)
{
    extern __shared__ uint32_t sm[];
    uint32_t* Qh = sm;
    uint32_t* Ql = sm + OFF_QL;
    const uint32_t sb = (uint32_t)__cvta_generic_to_shared(sm);

    const int qbx = gridDim.x - 1 - blockIdx.x;
    const int h   = blockIdx.y;
    const int b   = blockIdx.z;

    const int tid  = threadIdx.x;
    const int wid  = tid >> 5;
    const int lane = tid & 31;
    const int g = lane >> 2;
    const int t = lane & 3;

    const int qoff = h * 32;
    const int koff = 512 + h * 32;
    const int voff = 1024 + h * 32;

    const int wq = qbx * 128 + wid * 16;

#pragma unroll
    for (int it = 0; it < 16; it++) {
        int idx = tid + it * 256;
        int row = idx >> 5;
        int dp  = idx & 31;
        size_t gi = (size_t)(b * SEQ + qbx * 128 + row) * LD32 + qoff + dp;
        Qh[row * FSTR + dp] = qh[gi];
        Ql[row * FSTR + dp] = ql[gi];
    }

    const int crow = tid >> 3;
    const int cch  = tid & 7;
    auto issue_blk = [&](int jb, int buf) {
        const uint32_t base = sb + (uint32_t)((OFF_BUF + buf * BUF_SZ) * 4);
        const size_t trow = (size_t)(b * SEQ + jb * 64);
#pragma unroll
        for (int i = 0; i < 2; i++) {
            int row = crow + i * 32;
            uint32_t so = (uint32_t)(row * 144 + cch * 16);
            size_t gr = (trow + row) * LD32 + cch * 4;
            cp16(base + 0 * (PL_SZ * 4) + so, qh + gr + koff);
            cp16(base + 1 * (PL_SZ * 4) + so, ql + gr + koff);
            cp16(base + 2 * (PL_SZ * 4) + so, qh + gr + voff);
            cp16(base + 3 * (PL_SZ * 4) + so, ql + gr + voff);
        }
        CP_COMMIT();
    };

    const uint32_t qa   = sb + (uint32_t)((wid * 16 + (lane & 15)) * 144 +
                                          (lane >> 4) * 16);
    const uint32_t krow = (uint32_t)((lane & 7) + ((lane >> 4) & 1) * 8);
    const uint32_t kcol = (uint32_t)(((lane >> 3) & 1) * 16);
    const uint32_t vrow = (uint32_t)(lane & 15);
    const uint32_t vcol = (uint32_t)(((lane >> 4) & 1) * 16);

    float oa[8][4];
#pragma unroll
    for (int nt = 0; nt < 8; nt++)
#pragma unroll
        for (int r = 0; r < 4; r++) oa[nt][r] = 0.0f;
    float m0 = -1e30f, m1 = -1e30f, l0 = 0.0f, l1 = 0.0f;

    const int r0g = wq + g;
    const int r1g = wq + g + 8;
    const int nblocks = 2 * qbx + 2;

    issue_blk(0, 0);
    issue_blk(1, 1);

    for (int jb = 0; jb < nblocks; jb++) {
        if (jb + 1 < nblocks) CP_WAIT(1); else CP_WAIT(0);
        __syncthreads();

        if (jb * 64 <= wq + 15) {
            const uint32_t kbH = sb + (uint32_t)((OFF_BUF + (jb & 1) * BUF_SZ) * 4);
            const uint32_t kbL = kbH + PL_SZ * 4;
            const uint32_t vbH = kbL + PL_SZ * 4;
            const uint32_t vbL = vbH + PL_SZ * 4;

            float sc[8][4];
#pragma unroll
            for (int nt = 0; nt < 8; nt++)
#pragma unroll
                for (int r = 0; r < 4; r++) sc[nt][r] = 0.0f;

#pragma unroll
            for (int s = 0; s < 4; s++) {
                uint32_t q0, q1, q2, q3, p0, p1, p2, p3;
                ldsm4(q0, q1, q2, q3, qa + (uint32_t)(s * 32));
                ldsm4(p0, p1, p2, p3, qa + (uint32_t)(OFF_QL * 4 + s * 32));
#pragma unroll
                for (int np = 0; np < 4; np++) {
                    const uint32_t ro = (uint32_t)((np * 16 + krow) * 144) +
                                        (uint32_t)(s * 32) + kcol;
                    uint32_t kh0, kh1, kh2, kh3, kl0, kl1, kl2, kl3;
                    ldsm4(kh0, kh1, kh2, kh3, kbH + ro);
                    ldsm4(kl0, kl1, kl2, kl3, kbL + ro);
                    mma_bf16(sc[2 * np],     q0, q1, q2, q3, kh0, kh1);
                    mma_bf16(sc[2 * np],     q0, q1, q2, q3, kl0, kl1);
                    mma_bf16(sc[2 * np],     p0, p1, p2, p3, kh0, kh1);
                    mma_bf16(sc[2 * np + 1], q0, q1, q2, q3, kh2, kh3);
                    mma_bf16(sc[2 * np + 1], q0, q1, q2, q3, kl2, kl3);
                    mma_bf16(sc[2 * np + 1], p0, p1, p2, p3, kh2, kh3);
                }
            }

            if (jb * 64 + 63 > wq) {
#pragma unroll
                for (int nt = 0; nt < 8; nt++) {
                    int c = jb * 64 + nt * 8 + 2 * t;
                    if (c > r0g)     sc[nt][0] = -1e30f;
                    if (c + 1 > r0g) sc[nt][1] = -1e30f;
                    if (c > r1g)     sc[nt][2] = -1e30f;
                    if (c + 1 > r1g) sc[nt][3] = -1e30f;
                }
            }

            float mx0 = -1e30f, mx1 = -1e30f;
#pragma unroll
            for (int nt = 0; nt < 8; nt++) {
                mx0 = fmaxf(mx0, fmaxf(sc[nt][0], sc[nt][1]));
                mx1 = fmaxf(mx1, fmaxf(sc[nt][2], sc[nt][3]));
            }
#pragma unroll
            for (int off = 1; off <= 2; off <<= 1) {
                mx0 = fmaxf(mx0, __shfl_xor_sync(0xffffffffu, mx0, off));
                mx1 = fmaxf(mx1, __shfl_xor_sync(0xffffffffu, mx1, off));
            }
            float mn0 = fmaxf(m0, mx0), mn1 = fmaxf(m1, mx1);
            float corr0 = __expf(m0 - mn0), corr1 = __expf(m1 - mn1);
            float s0 = 0.0f, s1 = 0.0f;
#pragma unroll
            for (int nt = 0; nt < 8; nt++) {
                sc[nt][0] = __expf(sc[nt][0] - mn0);
                sc[nt][1] = __expf(sc[nt][1] - mn0);
                sc[nt][2] = __expf(sc[nt][2] - mn1);
                sc[nt][3] = __expf(sc[nt][3] - mn1);
                s0 += sc[nt][0] + sc[nt][1];
                s1 += sc[nt][2] + sc[nt][3];
            }
#pragma unroll
            for (int off = 1; off <= 2; off <<= 1) {
                s0 += __shfl_xor_sync(0xffffffffu, s0, off);
                s1 += __shfl_xor_sync(0xffffffffu, s1, off);
            }
            l0 = l0 * corr0 + s0;  m0 = mn0;
            l1 = l1 * corr1 + s1;  m1 = mn1;
#pragma unroll
            for (int nt = 0; nt < 8; nt++) {
                oa[nt][0] *= corr0;  oa[nt][1] *= corr0;
                oa[nt][2] *= corr1;  oa[nt][3] *= corr1;
            }

#pragma unroll
            for (int s = 0; s < 4; s++) {
                uint32_t ph[4];
                ph[0] = pack_h2(sc[2 * s][0],     sc[2 * s][1]);
                ph[1] = pack_h2(sc[2 * s][2],     sc[2 * s][3]);
                ph[2] = pack_h2(sc[2 * s + 1][0], sc[2 * s + 1][1]);
                ph[3] = pack_h2(sc[2 * s + 1][2], sc[2 * s + 1][3]);
#pragma unroll
                for (int np = 0; np < 4; np++) {
                    const uint32_t ro = (uint32_t)((s * 16 + vrow) * 144) +
                                        (uint32_t)(np * 32) + vcol;
                    uint32_t vh0, vh1, vh2, vh3, vl0, vl1, vl2, vl3;
                    ldsm4t(vh0, vh1, vh2, vh3, vbH + ro);
                    ldsm4t(vl0, vl1, vl2, vl3, vbL + ro);
                    mma_f16(oa[2 * np],     ph[0], ph[1], ph[2], ph[3], vh0, vh1);
                    mma_f16(oa[2 * np],     ph[0], ph[1], ph[2], ph[3], vl0, vl1);
                    mma_f16(oa[2 * np + 1], ph[0], ph[1], ph[2], ph[3], vh2, vh3);
                    mma_f16(oa[2 * np + 1], ph[0], ph[1], ph[2], ph[3], vl2, vl3);
                }
            }
        }

        __syncthreads();
        if (jb + 2 < nblocks) issue_blk(jb + 2, jb & 1);
    }

    // epilogue: store + block-level max|attn| (one atomic per CTA)
    const float inv0 = 1.0f / l0, inv1 = 1.0f / l1;
    const size_t orow0 = (size_t)(b * SEQ + r0g) * HIDDEN + h * HDIM;
    const size_t orow1 = (size_t)(b * SEQ + r1g) * HIDDEN + h * HDIM;
    float lmax = 0.0f;
#pragma unroll
    for (int nt = 0; nt < 8; nt++) {
        const int d = nt * 8 + 2 * t;
        float2 o0 = make_float2(oa[nt][0] * inv0, oa[nt][1] * inv0);
        float2 o1 = make_float2(oa[nt][2] * inv1, oa[nt][3] * inv1);
        *(float2*)(out + orow0 + d) = o0;
        *(float2*)(out + orow1 + d) = o1;
        lmax = fmaxf(lmax, fmaxf(fmaxf(fabsf(o0.x), fabsf(o0.y)),
                                 fmaxf(fabsf(o1.x), fabsf(o1.y))));
    }
#pragma unroll
    for (int off = 16; off >= 1; off >>= 1)
        lmax = fmaxf(lmax, __shfl_xor_sync(0xffffffffu, lmax, off));
    __syncthreads();
    float* red = (float*)sm;
    if (lane == 0) red[wid] = lmax;
    __syncthreads();
    if (tid == 0) {
        float bm = red[0];
#pragma unroll
        for (int w = 1; w < 8; w++) bm = fmaxf(bm, red[w]);
        atomicMax(&g_maxA, __float_as_uint(bm));
    }
}

// ---------------------------------------------------------------------------
// int8 2-digit GEMM + bias (R7 kernel, verbatim)
// ---------------------------------------------------------------------------
#define IA_PL 6144
#define IB_PL 3072
#define ISTG (2 * IA_PL + 2 * IB_PL)
#define INST 4
#define INT8_SMEM (INST * ISTG)      // 73728

__global__ __launch_bounds__(256, 2)
void gemm_int8(const int8_t* __restrict__ A1, const int8_t* __restrict__ A2,
               const int8_t* __restrict__ W1, const int8_t* __restrict__ W2,
               const float* __restrict__ bias, float* __restrict__ C,
               int M, int N, int K)
{
    extern __shared__ uint32_t smem[];
    const uint32_t sb = (uint32_t)__cvta_generic_to_shared(smem);

    const int tid  = threadIdx.x;
    const int warp = tid >> 5;
    const int lane = tid & 31;
    const int g = lane >> 2;
    const int t = lane & 3;
    const int wm = (warp >> 1) * 32;
    const int wn = (warp & 1) * 32;
    const int brow = blockIdx.y * 128;
    const int bcol = blockIdx.x * 64;

    const int arow = tid >> 1, ahalf = tid & 1;
    const int wrow = tid >> 2, whalf = (tid >> 1) & 1, wpl = tid & 1;
    const int8_t* gA[2] = { A1 + (size_t)(brow + arow) * K + ahalf * 16,
                            A2 + (size_t)(brow + arow) * K + ahalf * 16 };
    const int8_t* gW   = (wpl ? W2 : W1) + (size_t)(bcol + wrow) * K + whalf * 16;

    auto issue_chunk = [&](int c) {
        const uint32_t base = sb + (uint32_t)((c & (INST - 1)) * ISTG);
        const int k0 = c * 32;
        cp16(base + 0 * IA_PL + arow * 48 + ahalf * 16, gA[0] + k0);
        cp16(base + 1 * IA_PL + arow * 48 + ahalf * 16, gA[1] + k0);
        cp16(base + 2 * IA_PL + wpl * IB_PL + wrow * 48 + whalf * 16, gW + k0);
        CP_COMMIT();
    };

    const int laA = (lane & 7) + ((lane >> 3) & 1) * 8;
    const uint32_t kaA = (uint32_t)(((lane >> 4) & 1) * 16);
    const int laB = (lane & 7) + ((lane >> 4) & 1) * 8;
    const uint32_t kaB = (uint32_t)(((lane >> 3) & 1) * 16);

    int acc1[2][4][4], acc2[2][4][4];
#pragma unroll
    for (int mt = 0; mt < 2; mt++)
#pragma unroll
        for (int nt = 0; nt < 4; nt++)
#pragma unroll
            for (int r = 0; r < 4; r++) { acc1[mt][nt][r] = 0; acc2[mt][nt][r] = 0; }

    const int NC = K / 32;
#pragma unroll
    for (int s = 0; s < INST - 1; s++) issue_chunk(s);

    for (int c = 0; c < NC; c++) {
        CP_WAIT(INST - 2);
        __syncthreads();
        if (c + INST - 1 < NC) issue_chunk(c + INST - 1);

        const uint32_t base = sb + (uint32_t)((c & (INST - 1)) * ISTG);
        uint32_t b1[4][2], b2[4][2];
#pragma unroll
        for (int np = 0; np < 2; np++) {
            const uint32_t ro = (uint32_t)((wn + np * 16 + laB) * 48) + kaB;
            ldsm4(b1[2 * np][0], b1[2 * np][1], b1[2 * np + 1][0], b1[2 * np + 1][1],
                  base + 2 * IA_PL + ro);
            ldsm4(b2[2 * np][0], b2[2 * np][1], b2[2 * np + 1][0], b2[2 * np + 1][1],
                  base + 2 * IA_PL + IB_PL + ro);
        }
#pragma unroll
        for (int mt = 0; mt < 2; mt++) {
            const uint32_t ro = (uint32_t)((wm + mt * 16 + laA) * 48) + kaA;
            uint32_t a1f[4], a2f[4];
            ldsm4(a1f[0], a1f[1], a1f[2], a1f[3], base + ro);
            ldsm4(a2f[0], a2f[1], a2f[2], a2f[3], base + IA_PL + ro);
#pragma unroll
            for (int nt = 0; nt < 4; nt++) {
                mma_s8(acc1[mt][nt], a1f[0], a1f[1], a1f[2], a1f[3],
                       b1[nt][0], b1[nt][1]);
                mma_s8(acc2[mt][nt], a1f[0], a1f[1], a1f[2], a1f[3],
                       b2[nt][0], b2[nt][1]);
                mma_s8(acc2[mt][nt], a2f[0], a2f[1], a2f[2], a2f[3],
                       b1[nt][0], b1[nt][1]);
            }
        }
    }

    const float maxA = fmaxf(__uint_as_float(g_maxA), 1e-30f);
    const float maxW = fmaxf(__uint_as_float(g_maxW), 1e-30f);
    const float inv = (maxA * maxW) / (32512.0f * 32512.0f);

#pragma unroll
    for (int nt = 0; nt < 4; nt++) {
        const int col = bcol + wn + nt * 8 + 2 * t;
        const float2 bv = *(const float2*)(bias + col);
#pragma unroll
        for (int mt = 0; mt < 2; mt++) {
            const int row0 = brow + wm + mt * 16 + g;
            float2 o0, o1;
            o0.x = (65536.0f * (float)acc1[mt][nt][0] + 256.0f * (float)acc2[mt][nt][0]) * inv + bv.x;
            o0.y = (65536.0f * (float)acc1[mt][nt][1] + 256.0f * (float)acc2[mt][nt][1]) * inv + bv.y;
            o1.x = (65536.0f * (float)acc1[mt][nt][2] + 256.0f * (float)acc2[mt][nt][2]) * inv + bv.x;
            o1.y = (65536.0f * (float)acc1[mt][nt][3] + 256.0f * (float)acc2[mt][nt][3]) * inv + bv.y;
            *(float2*)(C + (size_t)row0 * N + col)       = o0;
            *(float2*)(C + (size_t)(row0 + 8) * N + col) = o1;
        }
    }
}

// ---------------------------------------------------------------------------
// Launch
// ---------------------------------------------------------------------------
extern "C" void kernel_launch(void* const* d_in, const int* in_sizes, int n_in,
                              void* d_out, int out_size)
{
    const float* hidden = (const float*)d_in[0];
    const float* w_attn = (const float*)d_in[1];
    const float* b_attn = (const float*)d_in[2];
    const float* w_proj = (const float*)d_in[3];
    const float* b_proj = (const float*)d_in[4];
    float* out = (float*)d_out;

    uint32_t *qh, *ql;
    float* attn;
    int8_t *a1, *a2, *w1, *w2;
    unsigned* mW;
    cudaGetSymbolAddress((void**)&qh, g_qh);
    cudaGetSymbolAddress((void**)&ql, g_ql);
    cudaGetSymbolAddress((void**)&attn, g_attn);
    cudaGetSymbolAddress((void**)&a1, g_a1);
    cudaGetSymbolAddress((void**)&a2, g_a2);
    cudaGetSymbolAddress((void**)&w1, g_w1);
    cudaGetSymbolAddress((void**)&w2, g_w2);
    cudaGetSymbolAddress((void**)&mW, g_maxW);

    static bool attr_set = false;
    if (!attr_set) {
        cudaFuncSetAttribute(flash_bf16x3,
                             cudaFuncAttributeMaxDynamicSharedMemorySize, FL_SMEM);
        cudaFuncSetAttribute(gemm_int8,
                             cudaFuncAttributeMaxDynamicSharedMemorySize, INT8_SMEM);
        attr_set = true;
    }

    // 0) w_proj max + transpose/quantize
    maxabs_kernel<<<256, 256>>>(w_proj, HIDDEN * HIDDEN, mW);
    {
        dim3 gp(HIDDEN / 32, HIDDEN / 64);
        transpose_quant_kernel<<<gp, 256>>>(w_proj, w1, w2, HIDDEN, HIDDEN);
    }
    // 1) QKV projection: Q,K bf16x3; V fp16 2-term
    {
        dim3 grid(QKV_N / 128, M_TOK / 128);
        gemm_bf16x3<<<grid, 256>>>(hidden, w_attn, b_attn,
                                   nullptr, qh, ql,
                                   M_TOK, QKV_N, HIDDEN, 1);
    }
    // 2) flash attention v4 -> fp32 attn + g_maxA
    {
        dim3 grid(SEQ / 128, NHEAD, BATCH);
        flash_bf16x3<<<grid, 256, FL_SMEM>>>(qh, ql, attn);
    }
    // 3) quantize attn to int8 digits
    {
        const int n = M_TOK * HIDDEN;
        quant_attn_kernel<<<(n + 255) / 256, 256>>>(attn, a1, a2, n);
    }
    // 4) output projection via int8 IMMA
    {
        dim3 grid(HIDDEN / 64, M_TOK / 128);
        gemm_int8<<<grid, 256, INT8_SMEM>>>(a1, a2, w1, w2, b_proj, out,
                                            M_TOK, HIDDEN, HIDDEN);
    }
}

// round 17
// speedup vs baseline: 1.0974x; 1.0420x over previous
#include <cuda_runtime.h>
#include <cuda_bf16.h>
#include <cuda_fp16.h>
#include <math.h>
#include <stdint.h>

// ---------------------------------------------------------------------------
// Problem constants
// ---------------------------------------------------------------------------
#define BATCH 2
#define SEQ 2048
#define HIDDEN 1024
#define NHEAD 16
#define HDIM 64
#define M_TOK (BATCH * SEQ)          // 4096
#define QKV_N (3 * HIDDEN)           // 3072
#define LD32 (QKV_N / 2)             // 1536 u32 per token row (qkv planes)

// Scratch (__device__ globals per allocation rules).
// Digit planes are 16B-aligned so vectorized u32/u128 access is legal.
__device__ uint32_t g_qh[(size_t)M_TOK * LD32];      // qkv hi plane (V range: fp16)
__device__ uint32_t g_ql[(size_t)M_TOK * LD32];      // qkv lo plane
__device__ float    g_attn[(size_t)M_TOK * HIDDEN];  // attention output fp32
__device__ __align__(16) int8_t g_a1[(size_t)M_TOK * HIDDEN];   // attn digit1
__device__ __align__(16) int8_t g_a2[(size_t)M_TOK * HIDDEN];   // attn digit2
__device__ __align__(16) int8_t g_w1[(size_t)HIDDEN * HIDDEN];  // w_proj^T digit1
__device__ __align__(16) int8_t g_w2[(size_t)HIDDEN * HIDDEN];  // w_proj^T digit2
__device__ unsigned g_maxA;                          // max|attn| (float bits)
__device__ unsigned g_maxW;                          // max|w_proj|

// ---------------------------------------------------------------------------
// Helpers
// ---------------------------------------------------------------------------
__device__ __forceinline__ void split2(float x, float y,
                                       uint32_t& hi, uint32_t& lo) {
    __nv_bfloat162 h = __floats2bfloat162_rn(x, y);
    float2 hf = __bfloat1622float2(h);
    __nv_bfloat162 l = __floats2bfloat162_rn(x - hf.x, y - hf.y);
    hi = *reinterpret_cast<uint32_t*>(&h);
    lo = *reinterpret_cast<uint32_t*>(&l);
}

// fp16 hi/lo split (pair reproduces fp32 to ~2^-23)
__device__ __forceinline__ void split2h(float x, float y,
                                        uint32_t& hi, uint32_t& lo) {
    __half2 h = __floats2half2_rn(x, y);
    float2 hf = __half22float2(h);
    __half2 l = __floats2half2_rn(x - hf.x, y - hf.y);
    hi = *reinterpret_cast<uint32_t*>(&h);
    lo = *reinterpret_cast<uint32_t*>(&l);
}

__device__ __forceinline__ uint32_t pack_h2(float x, float y) {
    __half2 h = __floats2half2_rn(x, y);
    return *reinterpret_cast<uint32_t*>(&h);
}

__device__ __forceinline__ void mma_bf16(float* c, uint32_t a0, uint32_t a1,
                                         uint32_t a2, uint32_t a3,
                                         uint32_t b0, uint32_t b1) {
    asm volatile(
        "mma.sync.aligned.m16n8k16.row.col.f32.bf16.bf16.f32 "
        "{%0,%1,%2,%3}, {%4,%5,%6,%7}, {%8,%9}, {%0,%1,%2,%3};"
        : "+f"(c[0]), "+f"(c[1]), "+f"(c[2]), "+f"(c[3])
        : "r"(a0), "r"(a1), "r"(a2), "r"(a3), "r"(b0), "r"(b1));
}

__device__ __forceinline__ void mma_f16(float* c, uint32_t a0, uint32_t a1,
                                        uint32_t a2, uint32_t a3,
                                        uint32_t b0, uint32_t b1) {
    asm volatile(
        "mma.sync.aligned.m16n8k16.row.col.f32.f16.f16.f32 "
        "{%0,%1,%2,%3}, {%4,%5,%6,%7}, {%8,%9}, {%0,%1,%2,%3};"
        : "+f"(c[0]), "+f"(c[1]), "+f"(c[2]), "+f"(c[3])
        : "r"(a0), "r"(a1), "r"(a2), "r"(a3), "r"(b0), "r"(b1));
}

__device__ __forceinline__ void mma_s8(int* c, uint32_t a0, uint32_t a1,
                                       uint32_t a2, uint32_t a3,
                                       uint32_t b0, uint32_t b1) {
    asm volatile(
        "mma.sync.aligned.m16n8k32.row.col.s32.s8.s8.s32 "
        "{%0,%1,%2,%3}, {%4,%5,%6,%7}, {%8,%9}, {%0,%1,%2,%3};"
        : "+r"(c[0]), "+r"(c[1]), "+r"(c[2]), "+r"(c[3])
        : "r"(a0), "r"(a1), "r"(a2), "r"(a3), "r"(b0), "r"(b1));
}

__device__ __forceinline__ void ldsm4(uint32_t& r0, uint32_t& r1,
                                      uint32_t& r2, uint32_t& r3, uint32_t a) {
    asm volatile("ldmatrix.sync.aligned.m8n8.x4.shared.b16 {%0,%1,%2,%3}, [%4];"
                 : "=r"(r0), "=r"(r1), "=r"(r2), "=r"(r3) : "r"(a));
}

__device__ __forceinline__ void ldsm4t(uint32_t& r0, uint32_t& r1,
                                       uint32_t& r2, uint32_t& r3, uint32_t a) {
    asm volatile("ldmatrix.sync.aligned.m8n8.x4.trans.shared.b16 {%0,%1,%2,%3}, [%4];"
                 : "=r"(r0), "=r"(r1), "=r"(r2), "=r"(r3) : "r"(a));
}

// streaming copy (no L1 reuse on this data -> .cg)
__device__ __forceinline__ void cp16(uint32_t smem, const void* gmem) {
    asm volatile("cp.async.cg.shared.global [%0], [%1], 16;"
                 :: "r"(smem), "l"(gmem));
}
#define CP_COMMIT() asm volatile("cp.async.commit_group;" ::: "memory")
#define CP_WAIT(n)  asm volatile("cp.async.wait_group %0;" :: "n"(n) : "memory")

// quantize x (|x| <= max) to q1*256 + q2 with S = 32512/max
__device__ __forceinline__ void quant2(float x, float S, int8_t& d1, int8_t& d2) {
    int q = __float2int_rn(x * S);
    int q1 = (q + 128) >> 8;
    d1 = (int8_t)q1;
    d2 = (int8_t)(q - (q1 << 8));
}

// ---------------------------------------------------------------------------
// max-abs reduction (vectorized)
// ---------------------------------------------------------------------------
__global__ __launch_bounds__(256)
void maxabs_kernel(const float4* __restrict__ x, int n4, unsigned* __restrict__ out)
{
    float m = 0.0f;
    for (int i = blockIdx.x * 256 + threadIdx.x; i < n4; i += gridDim.x * 256) {
        float4 v = x[i];
        m = fmaxf(m, fmaxf(fmaxf(fabsf(v.x), fabsf(v.y)),
                           fmaxf(fabsf(v.z), fabsf(v.w))));
    }
#pragma unroll
    for (int off = 16; off >= 1; off >>= 1)
        m = fmaxf(m, __shfl_xor_sync(0xffffffffu, m, off));
    if ((threadIdx.x & 31) == 0)
        atomicMax(out, __float_as_uint(m));
}

// ---------------------------------------------------------------------------
// quantize attn fp32 -> digit planes (vectorized; digit arrays are 16B-aligned)
// ---------------------------------------------------------------------------
__global__ __launch_bounds__(256)
void quant_attn_kernel(const float4* __restrict__ x,
                       uint32_t* __restrict__ d1, uint32_t* __restrict__ d2,
                       int n4)
{
    const float maxv = fmaxf(__uint_as_float(g_maxA), 1e-30f);
    const float S = 32512.0f / maxv;
    int i = blockIdx.x * 256 + threadIdx.x;
    if (i < n4) {
        float4 v = x[i];
        int8_t a[4], b[4];
        quant2(v.x, S, a[0], b[0]);
        quant2(v.y, S, a[1], b[1]);
        quant2(v.z, S, a[2], b[2]);
        quant2(v.w, S, a[3], b[3]);
        uint32_t ua, ub;
        memcpy(&ua, a, 4);
        memcpy(&ub, b, 4);
        d1[i] = ua;
        d2[i] = ub;
    }
}

// ---------------------------------------------------------------------------
// transpose + quantize  W[K][N] -> digit planes [N][K]
// ---------------------------------------------------------------------------
__global__ __launch_bounds__(256)
void transpose_quant_kernel(const float* __restrict__ W,
                            int8_t* __restrict__ d1, int8_t* __restrict__ d2,
                            int K, int N)
{
    __shared__ float s[64][33];
    const int tid = threadIdx.x;
    const int k0 = blockIdx.y * 64;
    const int n0 = blockIdx.x * 32;
    const float maxv = fmaxf(__uint_as_float(g_maxW), 1e-30f);
    const float S = 32512.0f / maxv;

#pragma unroll
    for (int i = 0; i < 8; i++) {
        int idx = tid + i * 256;
        int nl = idx & 31;
        int kl = idx >> 5;
        s[kl][nl] = W[(size_t)(k0 + kl) * N + n0 + nl];
    }
    __syncthreads();

#pragma unroll
    for (int i = 0; i < 8; i++) {
        int idx = tid + i * 256;
        int kl = idx & 63;
        int nl = idx >> 6;
        size_t o = (size_t)(n0 + nl) * K + k0 + kl;
        quant2(s[kl][nl], S, d1[o], d2[o]);
    }
}

// ---------------------------------------------------------------------------
// bf16x3 GEMM + bias (R11/R16 verbatim): C = A[M,K] @ B[K,N] + bias
// mode 0: fp32 C. mode 1: split planes (bf16 for cols<2048, fp16 for V cols).
// ---------------------------------------------------------------------------
#define GASTR 12
#define GBSTR 136

__global__ __launch_bounds__(256)
void gemm_bf16x3(const float* __restrict__ A, const float* __restrict__ B,
                 const float* __restrict__ bias,
                 float* __restrict__ Cf,
                 uint32_t* __restrict__ Chi, uint32_t* __restrict__ Clo,
                 int M, int N, int K, int mode)
{
    __shared__ uint32_t Ah[2][128 * GASTR], Al[2][128 * GASTR];
    __shared__ uint32_t Bh[2][8 * GBSTR],  Bl[2][8 * GBSTR];

    const int tid  = threadIdx.x;
    const int warp = tid >> 5;
    const int lane = tid & 31;
    const int g = lane >> 2;
    const int t = lane & 3;
    const int wm = (warp >> 2) * 64;
    const int wn = (warp & 3) * 32;
    const int brow = blockIdx.y * 128;
    const int bcol = blockIdx.x * 128;

    float acc[4][4][4];
#pragma unroll
    for (int mt = 0; mt < 4; mt++)
#pragma unroll
        for (int nt = 0; nt < 4; nt++)
#pragma unroll
            for (int r = 0; r < 4; r++) acc[mt][nt][r] = 0.0f;

    const int am[2] = { (tid + 0) >> 2, (tid + 256) >> 2 };
    const int aq[2] = { (tid + 0) & 3,  (tid + 256) & 3 };
    const int bkp   = tid >> 5;
    const int bn0   = (tid & 31) * 4;

    float4 pa[2], pb0, pb1;

    auto prefetch = [&](int k0) {
#pragma unroll
        for (int it = 0; it < 2; it++)
            pa[it] = *(const float4*)(A + (size_t)(brow + am[it]) * K + k0 + aq[it] * 4);
        pb0 = *(const float4*)(B + (size_t)(k0 + 2 * bkp) * N + bcol + bn0);
        pb1 = *(const float4*)(B + (size_t)(k0 + 2 * bkp + 1) * N + bcol + bn0);
    };
    auto stage = [&](int buf) {
#pragma unroll
        for (int it = 0; it < 2; it++) {
            uint32_t h0, l0, h1, l1;
            split2(pa[it].x, pa[it].y, h0, l0);
            split2(pa[it].z, pa[it].w, h1, l1);
            int base = am[it] * GASTR + aq[it] * 2;
            Ah[buf][base] = h0;  Ah[buf][base + 1] = h1;
            Al[buf][base] = l0;  Al[buf][base + 1] = l1;
        }
        uint32_t h[4], l[4];
        split2(pb0.x, pb1.x, h[0], l[0]);
        split2(pb0.y, pb1.y, h[1], l[1]);
        split2(pb0.z, pb1.z, h[2], l[2]);
        split2(pb0.w, pb1.w, h[3], l[3]);
        *(uint4*)&Bh[buf][bkp * GBSTR + bn0] = make_uint4(h[0], h[1], h[2], h[3]);
        *(uint4*)&Bl[buf][bkp * GBSTR + bn0] = make_uint4(l[0], l[1], l[2], l[3]);
    };

    prefetch(0);
    stage(0);
    __syncthreads();

    int buf = 0;
    for (int k0 = 0; k0 < K; k0 += 16) {
        const bool has_next = (k0 + 16) < K;
        if (has_next) prefetch(k0 + 16);

        uint32_t bh[4][2], bl[4][2];
#pragma unroll
        for (int nt = 0; nt < 4; nt++) {
            const int col = wn + nt * 8 + g;
            bh[nt][0] = Bh[buf][t * GBSTR + col];
            bh[nt][1] = Bh[buf][(t + 4) * GBSTR + col];
            bl[nt][0] = Bl[buf][t * GBSTR + col];
            bl[nt][1] = Bl[buf][(t + 4) * GBSTR + col];
        }
#pragma unroll
        for (int mt = 0; mt < 4; mt++) {
            const int r = wm + mt * 16 + g;
            uint32_t ah0 = Ah[buf][r * GASTR + t];
            uint32_t ah1 = Ah[buf][(r + 8) * GASTR + t];
            uint32_t ah2 = Ah[buf][r * GASTR + t + 4];
            uint32_t ah3 = Ah[buf][(r + 8) * GASTR + t + 4];
            uint32_t al0 = Al[buf][r * GASTR + t];
            uint32_t al1 = Al[buf][(r + 8) * GASTR + t];
            uint32_t al2 = Al[buf][r * GASTR + t + 4];
            uint32_t al3 = Al[buf][(r + 8) * GASTR + t + 4];
#pragma unroll
            for (int nt = 0; nt < 4; nt++) {
                mma_bf16(acc[mt][nt], ah0, ah1, ah2, ah3, bh[nt][0], bh[nt][1]);
                mma_bf16(acc[mt][nt], ah0, ah1, ah2, ah3, bl[nt][0], bl[nt][1]);
                mma_bf16(acc[mt][nt], al0, al1, al2, al3, bh[nt][0], bh[nt][1]);
            }
        }

        if (has_next) {
            stage(buf ^ 1);
            __syncthreads();
            buf ^= 1;
        }
    }

    const bool vregion = (bcol >= 2 * HIDDEN);   // V columns -> fp16 planes
#pragma unroll
    for (int nt = 0; nt < 4; nt++) {
        const int col = bcol + wn + nt * 8 + 2 * t;
        const float2 bv = *(const float2*)(bias + col);
#pragma unroll
        for (int mt = 0; mt < 4; mt++) {
            const int row0 = brow + wm + mt * 16 + g;
            float v00 = acc[mt][nt][0] + bv.x, v01 = acc[mt][nt][1] + bv.y;
            float v10 = acc[mt][nt][2] + bv.x, v11 = acc[mt][nt][3] + bv.y;
            if (mode == 0) {
                *(float2*)(Cf + (size_t)row0 * N + col)       = make_float2(v00, v01);
                *(float2*)(Cf + (size_t)(row0 + 8) * N + col) = make_float2(v10, v11);
            } else {
                uint32_t h, l;
                size_t i0 = ((size_t)row0 * N + col) >> 1;
                size_t i1 = ((size_t)(row0 + 8) * N + col) >> 1;
                if (vregion) {
                    split2h(v00, v01, h, l);  Chi[i0] = h;  Clo[i0] = l;
                    split2h(v10, v11, h, l);  Chi[i1] = h;  Clo[i1] = l;
                } else {
                    split2(v00, v01, h, l);   Chi[i0] = h;  Clo[i0] = l;
                    split2(v10, v11, h, l);   Chi[i1] = h;  Clo[i1] = l;
                }
            }
        }
    }
}

// ---------------------------------------------------------------------------
// Flash attention v4 (R11/R16 verbatim): QK^T bf16x3, PV fp16 2-term,
// fused block-level max|attn| (one atomic per CTA).
// ---------------------------------------------------------------------------
#define FSTR 36
#define OFF_QL (128 * FSTR)
#define OFF_BUF (2 * 128 * FSTR)
#define BUF_SZ  (4 * 64 * FSTR)
#define PL_SZ   (64 * FSTR)
#define FL_SMEM ((OFF_BUF + 2 * BUF_SZ) * 4)   // 110592 bytes

__global__ __launch_bounds__(256, 2)
void flash_bf16x3(const uint32_t* __restrict__ qh,
                  const uint32_t* __restrict__ ql,
                  float* __restrict__ out)
{
    extern __shared__ uint32_t sm[];
    uint32_t* Qh = sm;
    uint32_t* Ql = sm + OFF_QL;
    const uint32_t sb = (uint32_t)__cvta_generic_to_shared(sm);

    const int qbx = gridDim.x - 1 - blockIdx.x;
    const int h   = blockIdx.y;
    const int b   = blockIdx.z;

    const int tid  = threadIdx.x;
    const int wid  = tid >> 5;
    const int lane = tid & 31;
    const int g = lane >> 2;
    const int t = lane & 3;

    const int qoff = h * 32;
    const int koff = 512 + h * 32;
    const int voff = 1024 + h * 32;

    const int wq = qbx * 128 + wid * 16;

#pragma unroll
    for (int it = 0; it < 16; it++) {
        int idx = tid + it * 256;
        int row = idx >> 5;
        int dp  = idx & 31;
        size_t gi = (size_t)(b * SEQ + qbx * 128 + row) * LD32 + qoff + dp;
        Qh[row * FSTR + dp] = qh[gi];
        Ql[row * FSTR + dp] = ql[gi];
    }

    const int crow = tid >> 3;
    const int cch  = tid & 7;
    auto issue_blk = [&](int jb, int buf) {
        const uint32_t base = sb + (uint32_t)((OFF_BUF + buf * BUF_SZ) * 4);
        const size_t trow = (size_t)(b * SEQ + jb * 64);
#pragma unroll
        for (int i = 0; i < 2; i++) {
            int row = crow + i * 32;
            uint32_t so = (uint32_t)(row * 144 + cch * 16);
            size_t gr = (trow + row) * LD32 + cch * 4;
            cp16(base + 0 * (PL_SZ * 4) + so, qh + gr + koff);
            cp16(base + 1 * (PL_SZ * 4) + so, ql + gr + koff);
            cp16(base + 2 * (PL_SZ * 4) + so, qh + gr + voff);
            cp16(base + 3 * (PL_SZ * 4) + so, ql + gr + voff);
        }
        CP_COMMIT();
    };

    const uint32_t qa   = sb + (uint32_t)((wid * 16 + (lane & 15)) * 144 +
                                          (lane >> 4) * 16);
    const uint32_t krow = (uint32_t)((lane & 7) + ((lane >> 4) & 1) * 8);
    const uint32_t kcol = (uint32_t)(((lane >> 3) & 1) * 16);
    const uint32_t vrow = (uint32_t)(lane & 15);
    const uint32_t vcol = (uint32_t)(((lane >> 4) & 1) * 16);

    float oa[8][4];
#pragma unroll
    for (int nt = 0; nt < 8; nt++)
#pragma unroll
        for (int r = 0; r < 4; r++) oa[nt][r] = 0.0f;
    float m0 = -1e30f, m1 = -1e30f, l0 = 0.0f, l1 = 0.0f;

    const int r0g = wq + g;
    const int r1g = wq + g + 8;
    const int nblocks = 2 * qbx + 2;

    issue_blk(0, 0);
    issue_blk(1, 1);

    for (int jb = 0; jb < nblocks; jb++) {
        if (jb + 1 < nblocks) CP_WAIT(1); else CP_WAIT(0);
        __syncthreads();

        if (jb * 64 <= wq + 15) {
            const uint32_t kbH = sb + (uint32_t)((OFF_BUF + (jb & 1) * BUF_SZ) * 4);
            const uint32_t kbL = kbH + PL_SZ * 4;
            const uint32_t vbH = kbL + PL_SZ * 4;
            const uint32_t vbL = vbH + PL_SZ * 4;

            float sc[8][4];
#pragma unroll
            for (int nt = 0; nt < 8; nt++)
#pragma unroll
                for (int r = 0; r < 4; r++) sc[nt][r] = 0.0f;

#pragma unroll
            for (int s = 0; s < 4; s++) {
                uint32_t q0, q1, q2, q3, p0, p1, p2, p3;
                ldsm4(q0, q1, q2, q3, qa + (uint32_t)(s * 32));
                ldsm4(p0, p1, p2, p3, qa + (uint32_t)(OFF_QL * 4 + s * 32));
#pragma unroll
                for (int np = 0; np < 4; np++) {
                    const uint32_t ro = (uint32_t)((np * 16 + krow) * 144) +
                                        (uint32_t)(s * 32) + kcol;
                    uint32_t kh0, kh1, kh2, kh3, kl0, kl1, kl2, kl3;
                    ldsm4(kh0, kh1, kh2, kh3, kbH + ro);
                    ldsm4(kl0, kl1, kl2, kl3, kbL + ro);
                    mma_bf16(sc[2 * np],     q0, q1, q2, q3, kh0, kh1);
                    mma_bf16(sc[2 * np],     q0, q1, q2, q3, kl0, kl1);
                    mma_bf16(sc[2 * np],     p0, p1, p2, p3, kh0, kh1);
                    mma_bf16(sc[2 * np + 1], q0, q1, q2, q3, kh2, kh3);
                    mma_bf16(sc[2 * np + 1], q0, q1, q2, q3, kl2, kl3);
                    mma_bf16(sc[2 * np + 1], p0, p1, p2, p3, kh2, kh3);
                }
            }

            if (jb * 64 + 63 > wq) {
#pragma unroll
                for (int nt = 0; nt < 8; nt++) {
                    int c = jb * 64 + nt * 8 + 2 * t;
                    if (c > r0g)     sc[nt][0] = -1e30f;
                    if (c + 1 > r0g) sc[nt][1] = -1e30f;
                    if (c > r1g)     sc[nt][2] = -1e30f;
                    if (c + 1 > r1g) sc[nt][3] = -1e30f;
                }
            }

            float mx0 = -1e30f, mx1 = -1e30f;
#pragma unroll
            for (int nt = 0; nt < 8; nt++) {
                mx0 = fmaxf(mx0, fmaxf(sc[nt][0], sc[nt][1]));
                mx1 = fmaxf(mx1, fmaxf(sc[nt][2], sc[nt][3]));
            }
#pragma unroll
            for (int off = 1; off <= 2; off <<= 1) {
                mx0 = fmaxf(mx0, __shfl_xor_sync(0xffffffffu, mx0, off));
                mx1 = fmaxf(mx1, __shfl_xor_sync(0xffffffffu, mx1, off));
            }
            float mn0 = fmaxf(m0, mx0), mn1 = fmaxf(m1, mx1);
            float corr0 = __expf(m0 - mn0), corr1 = __expf(m1 - mn1);
            float s0 = 0.0f, s1 = 0.0f;
#pragma unroll
            for (int nt = 0; nt < 8; nt++) {
                sc[nt][0] = __expf(sc[nt][0] - mn0);
                sc[nt][1] = __expf(sc[nt][1] - mn0);
                sc[nt][2] = __expf(sc[nt][2] - mn1);
                sc[nt][3] = __expf(sc[nt][3] - mn1);
                s0 += sc[nt][0] + sc[nt][1];
                s1 += sc[nt][2] + sc[nt][3];
            }
#pragma unroll
            for (int off = 1; off <= 2; off <<= 1) {
                s0 += __shfl_xor_sync(0xffffffffu, s0, off);
                s1 += __shfl_xor_sync(0xffffffffu, s1, off);
            }
            l0 = l0 * corr0 + s0;  m0 = mn0;
            l1 = l1 * corr1 + s1;  m1 = mn1;
#pragma unroll
            for (int nt = 0; nt < 8; nt++) {
                oa[nt][0] *= corr0;  oa[nt][1] *= corr0;
                oa[nt][2] *= corr1;  oa[nt][3] *= corr1;
            }

#pragma unroll
            for (int s = 0; s < 4; s++) {
                uint32_t ph[4];
                ph[0] = pack_h2(sc[2 * s][0],     sc[2 * s][1]);
                ph[1] = pack_h2(sc[2 * s][2],     sc[2 * s][3]);
                ph[2] = pack_h2(sc[2 * s + 1][0], sc[2 * s + 1][1]);
                ph[3] = pack_h2(sc[2 * s + 1][2], sc[2 * s + 1][3]);
#pragma unroll
                for (int np = 0; np < 4; np++) {
                    const uint32_t ro = (uint32_t)((s * 16 + vrow) * 144) +
                                        (uint32_t)(np * 32) + vcol;
                    uint32_t vh0, vh1, vh2, vh3, vl0, vl1, vl2, vl3;
                    ldsm4t(vh0, vh1, vh2, vh3, vbH + ro);
                    ldsm4t(vl0, vl1, vl2, vl3, vbL + ro);
                    mma_f16(oa[2 * np],     ph[0], ph[1], ph[2], ph[3], vh0, vh1);
                    mma_f16(oa[2 * np],     ph[0], ph[1], ph[2], ph[3], vl0, vl1);
                    mma_f16(oa[2 * np + 1], ph[0], ph[1], ph[2], ph[3], vh2, vh3);
                    mma_f16(oa[2 * np + 1], ph[0], ph[1], ph[2], ph[3], vl2, vl3);
                }
            }
        }

        __syncthreads();
        if (jb + 2 < nblocks) issue_blk(jb + 2, jb & 1);
    }

    // epilogue: store + block-level max|attn| (one atomic per CTA)
    const float inv0 = 1.0f / l0, inv1 = 1.0f / l1;
    const size_t orow0 = (size_t)(b * SEQ + r0g) * HIDDEN + h * HDIM;
    const size_t orow1 = (size_t)(b * SEQ + r1g) * HIDDEN + h * HDIM;
    float lmax = 0.0f;
#pragma unroll
    for (int nt = 0; nt < 8; nt++) {
        const int d = nt * 8 + 2 * t;
        float2 o0 = make_float2(oa[nt][0] * inv0, oa[nt][1] * inv0);
        float2 o1 = make_float2(oa[nt][2] * inv1, oa[nt][3] * inv1);
        *(float2*)(out + orow0 + d) = o0;
        *(float2*)(out + orow1 + d) = o1;
        lmax = fmaxf(lmax, fmaxf(fmaxf(fabsf(o0.x), fabsf(o0.y)),
                                 fmaxf(fabsf(o1.x), fabsf(o1.y))));
    }
#pragma unroll
    for (int off = 16; off >= 1; off >>= 1)
        lmax = fmaxf(lmax, __shfl_xor_sync(0xffffffffu, lmax, off));
    __syncthreads();
    float* red = (float*)sm;
    if (lane == 0) red[wid] = lmax;
    __syncthreads();
    if (tid == 0) {
        float bm = red[0];
#pragma unroll
        for (int w = 1; w < 8; w++) bm = fmaxf(bm, red[w]);
        atomicMax(&g_maxA, __float_as_uint(bm));
    }
}

// ---------------------------------------------------------------------------
// int8 2-digit GEMM + bias (R11/R16 verbatim)
// ---------------------------------------------------------------------------
#define IA_PL 6144
#define IB_PL 3072
#define ISTG (2 * IA_PL + 2 * IB_PL)
#define INST 4
#define INT8_SMEM (INST * ISTG)      // 73728

__global__ __launch_bounds__(256, 2)
void gemm_int8(const int8_t* __restrict__ A1, const int8_t* __restrict__ A2,
               const int8_t* __restrict__ W1, const int8_t* __restrict__ W2,
               const float* __restrict__ bias, float* __restrict__ C,
               int M, int N, int K)
{
    extern __shared__ uint32_t smem[];
    const uint32_t sb = (uint32_t)__cvta_generic_to_shared(smem);

    const int tid  = threadIdx.x;
    const int warp = tid >> 5;
    const int lane = tid & 31;
    const int g = lane >> 2;
    const int t = lane & 3;
    const int wm = (warp >> 1) * 32;
    const int wn = (warp & 1) * 32;
    const int brow = blockIdx.y * 128;
    const int bcol = blockIdx.x * 64;

    const int arow = tid >> 1, ahalf = tid & 1;
    const int wrow = tid >> 2, whalf = (tid >> 1) & 1, wpl = tid & 1;
    const int8_t* gA[2] = { A1 + (size_t)(brow + arow) * K + ahalf * 16,
                            A2 + (size_t)(brow + arow) * K + ahalf * 16 };
    const int8_t* gW   = (wpl ? W2 : W1) + (size_t)(bcol + wrow) * K + whalf * 16;

    auto issue_chunk = [&](int c) {
        const uint32_t base = sb + (uint32_t)((c & (INST - 1)) * ISTG);
        const int k0 = c * 32;
        cp16(base + 0 * IA_PL + arow * 48 + ahalf * 16, gA[0] + k0);
        cp16(base + 1 * IA_PL + arow * 48 + ahalf * 16, gA[1] + k0);
        cp16(base + 2 * IA_PL + wpl * IB_PL + wrow * 48 + whalf * 16, gW + k0);
        CP_COMMIT();
    };

    const int laA = (lane & 7) + ((lane >> 3) & 1) * 8;
    const uint32_t kaA = (uint32_t)(((lane >> 4) & 1) * 16);
    const int laB = (lane & 7) + ((lane >> 4) & 1) * 8;
    const uint32_t kaB = (uint32_t)(((lane >> 3) & 1) * 16);

    int acc1[2][4][4], acc2[2][4][4];
#pragma unroll
    for (int mt = 0; mt < 2; mt++)
#pragma unroll
        for (int nt = 0; nt < 4; nt++)
#pragma unroll
            for (int r = 0; r < 4; r++) { acc1[mt][nt][r] = 0; acc2[mt][nt][r] = 0; }

    const int NC = K / 32;
#pragma unroll
    for (int s = 0; s < INST - 1; s++) issue_chunk(s);

    for (int c = 0; c < NC; c++) {
        CP_WAIT(INST - 2);
        __syncthreads();
        if (c + INST - 1 < NC) issue_chunk(c + INST - 1);

        const uint32_t base = sb + (uint32_t)((c & (INST - 1)) * ISTG);
        uint32_t b1[4][2], b2[4][2];
#pragma unroll
        for (int np = 0; np < 2; np++) {
            const uint32_t ro = (uint32_t)((wn + np * 16 + laB) * 48) + kaB;
            ldsm4(b1[2 * np][0], b1[2 * np][1], b1[2 * np + 1][0], b1[2 * np + 1][1],
                  base + 2 * IA_PL + ro);
            ldsm4(b2[2 * np][0], b2[2 * np][1], b2[2 * np + 1][0], b2[2 * np + 1][1],
                  base + 2 * IA_PL + IB_PL + ro);
        }
#pragma unroll
        for (int mt = 0; mt < 2; mt++) {
            const uint32_t ro = (uint32_t)((wm + mt * 16 + laA) * 48) + kaA;
            uint32_t a1f[4], a2f[4];
            ldsm4(a1f[0], a1f[1], a1f[2], a1f[3], base + ro);
            ldsm4(a2f[0], a2f[1], a2f[2], a2f[3], base + IA_PL + ro);
#pragma unroll
            for (int nt = 0; nt < 4; nt++) {
                mma_s8(acc1[mt][nt], a1f[0], a1f[1], a1f[2], a1f[3],
                       b1[nt][0], b1[nt][1]);
                mma_s8(acc2[mt][nt], a1f[0], a1f[1], a1f[2], a1f[3],
                       b2[nt][0], b2[nt][1]);
                mma_s8(acc2[mt][nt], a2f[0], a2f[1], a2f[2], a2f[3],
                       b1[nt][0], b1[nt][1]);
            }
        }
    }

    const float maxA = fmaxf(__uint_as_float(g_maxA), 1e-30f);
    const float maxW = fmaxf(__uint_as_float(g_maxW), 1e-30f);
    const float inv = (maxA * maxW) / (32512.0f * 32512.0f);

#pragma unroll
    for (int nt = 0; nt < 4; nt++) {
        const int col = bcol + wn + nt * 8 + 2 * t;
        const float2 bv = *(const float2*)(bias + col);
#pragma unroll
        for (int mt = 0; mt < 2; mt++) {
            const int row0 = brow + wm + mt * 16 + g;
            float2 o0, o1;
            o0.x = (65536.0f * (float)acc1[mt][nt][0] + 256.0f * (float)acc2[mt][nt][0]) * inv + bv.x;
            o0.y = (65536.0f * (float)acc1[mt][nt][1] + 256.0f * (float)acc2[mt][nt][1]) * inv + bv.y;
            o1.x = (65536.0f * (float)acc1[mt][nt][2] + 256.0f * (float)acc2[mt][nt][2]) * inv + bv.x;
            o1.y = (65536.0f * (float)acc1[mt][nt][3] + 256.0f * (float)acc2[mt][nt][3]) * inv + bv.y;
            *(float2*)(C + (size_t)row0 * N + col)       = o0;
            *(float2*)(C + (size_t)(row0 + 8) * N + col) = o1;
        }
    }
}

// ---------------------------------------------------------------------------
// Launch
// ---------------------------------------------------------------------------
extern "C" void kernel_launch(void* const* d_in, const int* in_sizes, int n_in,
                              void* d_out, int out_size)
{
    const float* hidden = (const float*)d_in[0];
    const float* w_attn = (const float*)d_in[1];
    const float* b_attn = (const float*)d_in[2];
    const float* w_proj = (const float*)d_in[3];
    const float* b_proj = (const float*)d_in[4];
    float* out = (float*)d_out;

    uint32_t *qh, *ql;
    float* attn;
    int8_t *a1, *a2, *w1, *w2;
    unsigned* mW;
    cudaGetSymbolAddress((void**)&qh, g_qh);
    cudaGetSymbolAddress((void**)&ql, g_ql);
    cudaGetSymbolAddress((void**)&attn, g_attn);
    cudaGetSymbolAddress((void**)&a1, g_a1);
    cudaGetSymbolAddress((void**)&a2, g_a2);
    cudaGetSymbolAddress((void**)&w1, g_w1);
    cudaGetSymbolAddress((void**)&w2, g_w2);
    cudaGetSymbolAddress((void**)&mW, g_maxW);

    static bool attr_set = false;
    if (!attr_set) {
        cudaFuncSetAttribute(flash_bf16x3,
                             cudaFuncAttributeMaxDynamicSharedMemorySize, FL_SMEM);
        cudaFuncSetAttribute(gemm_int8,
                             cudaFuncAttributeMaxDynamicSharedMemorySize, INT8_SMEM);
        attr_set = true;
    }

    // 0) w_proj max + transpose/quantize
    maxabs_kernel<<<128, 256>>>((const float4*)w_proj, (HIDDEN * HIDDEN) / 4, mW);
    {
        dim3 gp(HIDDEN / 32, HIDDEN / 64);
        transpose_quant_kernel<<<gp, 256>>>(w_proj, w1, w2, HIDDEN, HIDDEN);
    }
    // 1) QKV projection: Q,K bf16x3; V fp16 2-term
    {
        dim3 grid(QKV_N / 128, M_TOK / 128);
        gemm_bf16x3<<<grid, 256>>>(hidden, w_attn, b_attn,
                                   nullptr, qh, ql,
                                   M_TOK, QKV_N, HIDDEN, 1);
    }
    // 2) flash attention v4 -> fp32 attn + g_maxA
    {
        dim3 grid(SEQ / 128, NHEAD, BATCH);
        flash_bf16x3<<<grid, 256, FL_SMEM>>>(qh, ql, attn);
    }
    // 3) quantize attn to int8 digits (vectorized; arrays 16B-aligned)
    {
        const int n4 = (M_TOK * HIDDEN) / 4;
        quant_attn_kernel<<<(n4 + 255) / 256, 256>>>((const float4*)attn,
                                                     (uint32_t*)a1, (uint32_t*)a2,
                                                     n4);
    }
    // 4) output projection via int8 IMMA
    {
        dim3 grid(HIDDEN / 64, M_TOK / 128);
        gemm_int8<<<grid, 256, INT8_SMEM>>>(a1, a2, w1, w2, b_proj, out,
                                            M_TOK, HIDDEN, HIDDEN);
    }
}